// round 2
// baseline (speedup 1.0000x reference)
#include <cuda_runtime.h>
#include <math.h>

#define BB 16
#define TT 256
#define DD 128
#define HH 128
#define LL 4
#define GG (4*HH)      // 512 gates
#define NC 10
#define EPSF 1e-5f
#define BT (BB*TT)     // 4096

// ---------------- scratch (device globals; no allocation allowed) ----------------
__device__ float g_x2[BT*DD];      // normalized input
__device__ float g_gin[BT*GG];     // per-layer input-gemm result (reused)
__device__ float g_bufA[BT*HH];
__device__ float g_bufB[BT*HH];
__device__ float g_ln[BT*HH];      // instnorm(lstm_out)
__device__ float g_ph[BT*HH];
__device__ float g_px[BT*HH];
__device__ float g_mu[DD];
__device__ float g_sd[DD];
__device__ float g_s[BT];          // attention logits per (b,t)
__device__ float g_p[BT];          // softmax over t
__device__ float g_ctx[BB*HH];
__device__ float g_fc_scratch[BB*NC];
__device__ float g_map_scratch[BT*DD];

// ---------------- helpers ----------------
__device__ __forceinline__ float warpSum(float v) {
    #pragma unroll
    for (int o = 16; o > 0; o >>= 1) v += __shfl_xor_sync(0xffffffffu, v, o);
    return v;
}
__device__ __forceinline__ float sigf(float x) { return 1.0f / (1.0f + expf(-x)); }

// ---------------- per-feature global mean / std (ddof=1), std+EPS ----------------
__global__ void stats_kernel(const float* __restrict__ x) {
    int d = blockIdx.x;
    float s = 0.f, s2 = 0.f;
    for (int i = threadIdx.x; i < BT; i += blockDim.x) {
        float v = x[i*DD + d];
        s += v; s2 += v*v;
    }
    __shared__ float sh[64];
    s = warpSum(s); s2 = warpSum(s2);
    int w = threadIdx.x >> 5, ln = threadIdx.x & 31;
    if (ln == 0) { sh[w] = s; sh[32+w] = s2; }
    __syncthreads();
    if (threadIdx.x == 0) {
        float S = 0.f, S2 = 0.f;
        int nw = blockDim.x >> 5;
        for (int i = 0; i < nw; i++) { S += sh[i]; S2 += sh[32+i]; }
        float m = S / (float)BT;
        float var = (S2 - (float)BT*m*m) / ((float)BT - 1.0f);
        g_mu[d] = m;
        g_sd[d] = sqrtf(var) + EPSF;   // EPS added to std (torch-style)
    }
}

// ---------------- global normalize + instance norm over T, fused ----------------
__global__ void norm1_kernel(const float* __restrict__ x) {
    int b = blockIdx.x / DD, d = blockIdx.x % DD;
    int t = threadIdx.x;                  // 256 threads == T
    float mu = g_mu[d], sd = g_sd[d];
    float v = x[((b*TT) + t)*DD + d];
    float x1 = (v - mu) / sd;
    __shared__ float sh[16];
    float s = warpSum(x1), s2 = warpSum(x1*x1);
    int w = t >> 5, ln = t & 31;
    if (ln == 0) { sh[w] = s; sh[8+w] = s2; }
    __syncthreads();
    __shared__ float mm, rs;
    if (t == 0) {
        float S = 0.f, S2 = 0.f;
        for (int i = 0; i < 8; i++) { S += sh[i]; S2 += sh[8+i]; }
        float m = S / (float)TT;
        float var = S2 / (float)TT - m*m;  // biased
        mm = m; rs = rsqrtf(var + EPSF);
    }
    __syncthreads();
    g_x2[((b*TT) + t)*DD + d] = (x1 - mm) * rs;
}

// ---------------- generic instance norm over T per (b,c) ----------------
__global__ void instnorm_kernel(const float* __restrict__ in, float* __restrict__ out, int C) {
    int b = blockIdx.x / C, c = blockIdx.x % C;
    int t = threadIdx.x;
    float v = in[((b*TT) + t)*C + c];
    __shared__ float sh[16];
    float s = warpSum(v), s2 = warpSum(v*v);
    int w = t >> 5, ln = t & 31;
    if (ln == 0) { sh[w] = s; sh[8+w] = s2; }
    __syncthreads();
    __shared__ float mm, rs;
    if (t == 0) {
        float S = 0.f, S2 = 0.f;
        for (int i = 0; i < 8; i++) { S += sh[i]; S2 += sh[8+i]; }
        float m = S / (float)TT;
        float var = S2 / (float)TT - m*m;
        mm = m; rs = rsqrtf(var + EPSF);
    }
    __syncthreads();
    out[((b*TT) + t)*C + c] = (v - mm) * rs;
}

// ---------------- C[m,j] = sum_k A[m,k]*W[j,k] + b1[j] (+ b2[j]); K=128 ----------------
// blockDim.x == N (128 or 512); each block handles 16 rows of A.
__global__ void __launch_bounds__(512, 2) gemm16_kernel(
    const float* __restrict__ A, const float* __restrict__ W,
    const float* __restrict__ b1, const float* __restrict__ b2,
    float* __restrict__ C, int N)
{
    __shared__ __align__(16) float As[16*128];
    int m0 = blockIdx.x * 16;
    for (int idx = threadIdx.x; idx < 16*128; idx += blockDim.x)
        As[idx] = A[m0*128 + idx];
    __syncthreads();
    int j = threadIdx.x;
    float bias = b1[j] + (b2 ? b2[j] : 0.0f);
    float acc[16];
    #pragma unroll
    for (int mi = 0; mi < 16; mi++) acc[mi] = bias;
    const float4* W4 = reinterpret_cast<const float4*>(W) + j*32;
    for (int k4 = 0; k4 < 32; k4++) {
        float4 w = W4[k4];
        #pragma unroll
        for (int mi = 0; mi < 16; mi++) {
            float4 a = *reinterpret_cast<const float4*>(&As[mi*128 + k4*4]);
            acc[mi] += a.x*w.x + a.y*w.y + a.z*w.z + a.w*w.w;
        }
    }
    #pragma unroll
    for (int mi = 0; mi < 16; mi++) C[(m0+mi)*N + j] = acc[mi];
}

// ---------------- LSTM recurrence for one layer: grid=B, block=512 (one thread per gate) --------
__global__ void __launch_bounds__(512, 2) lstm_rec_kernel(
    const float* __restrict__ gin, const float* __restrict__ Whh,
    float* __restrict__ out)
{
    int b = blockIdx.x;
    int j = threadIdx.x;                 // gate index 0..511
    __shared__ __align__(16) float h_s[HH];
    __shared__ float gates[GG];
    float c = 0.0f;
    if (j < HH) h_s[j] = 0.0f;
    __syncthreads();
    const float4* W4 = reinterpret_cast<const float4*>(Whh) + j*32;
    const float* gin_b = gin + b*TT*GG;
    for (int t = 0; t < TT; t++) {
        float acc = gin_b[t*GG + j];
        #pragma unroll
        for (int k4 = 0; k4 < 32; k4++) {
            float4 w = W4[k4];
            float4 h4 = *reinterpret_cast<const float4*>(&h_s[k4*4]);
            acc += h4.x*w.x + h4.y*w.y + h4.z*w.z + h4.w*w.w;
        }
        gates[j] = acc;
        __syncthreads();
        if (j < HH) {
            float gi = gates[j], gf = gates[HH+j], gg = gates[2*HH+j], go = gates[3*HH+j];
            c = sigf(gf)*c + sigf(gi)*tanhf(gg);
            float hn = sigf(go)*tanhf(c);
            h_s[j] = hn;
            out[(b*TT + t)*HH + j] = hn;
        }
        __syncthreads();
    }
}

// ---------------- attention logit s[b,t] = sum_h tanh(ph+px)*aw[h] ----------------
__global__ void attn_s_kernel(const float* __restrict__ ph, const float* __restrict__ px,
                              const float* __restrict__ aw)
{
    int bt = blockIdx.x;
    int h = threadIdx.x;                 // 128
    float v = tanhf(ph[bt*HH + h] + px[bt*HH + h]) * aw[h];
    __shared__ float sh[4];
    v = warpSum(v);
    if ((h & 31) == 0) sh[h >> 5] = v;
    __syncthreads();
    if (h == 0) g_s[bt] = sh[0] + sh[1] + sh[2] + sh[3];
}

// ---------------- softmax over t (per b) + write attention map p_t/128 ----------------
__global__ void softmax_map_kernel(float* __restrict__ out_map) {
    int b = blockIdx.x, t = threadIdx.x;  // 256 threads
    float v = g_s[b*TT + t];
    __shared__ float sh[8];
    __shared__ float bc;
    // max
    float m = v;
    #pragma unroll
    for (int o = 16; o > 0; o >>= 1) m = fmaxf(m, __shfl_xor_sync(0xffffffffu, m, o));
    if ((t & 31) == 0) sh[t >> 5] = m;
    __syncthreads();
    if (t == 0) {
        float M = sh[0];
        for (int i = 1; i < 8; i++) M = fmaxf(M, sh[i]);
        bc = M;
    }
    __syncthreads();
    float M = bc;
    float e = expf(v - M);
    __syncthreads();
    float s = warpSum(e);
    if ((t & 31) == 0) sh[t >> 5] = s;
    __syncthreads();
    if (t == 0) {
        float S = 0.f;
        for (int i = 0; i < 8; i++) S += sh[i];
        bc = S;
    }
    __syncthreads();
    float p = e / bc;
    g_p[b*TT + t] = p;
    __shared__ float ps[TT];
    ps[t] = p * (1.0f / (float)DD);
    __syncthreads();
    const int base = b*TT*DD;
    for (int idx = t; idx < TT*DD; idx += TT)
        out_map[base + idx] = ps[idx >> 7];   // idx = t*128 + d
}

// ---------------- context[b,h] = sum_t ph[b,t,h] * p[b,t] ----------------
__global__ void context_kernel(const float* __restrict__ ph) {
    int b = blockIdx.x, h = threadIdx.x;   // 128 threads
    __shared__ float ps[TT];
    ps[h] = g_p[b*TT + h];
    ps[h + 128] = g_p[b*TT + h + 128];
    __syncthreads();
    float acc = 0.f;
    for (int t = 0; t < TT; t++)
        acc += ph[(b*TT + t)*HH + h] * ps[t];
    g_ctx[b*HH + h] = acc;
}

// ---------------- out[b,c] = ctx[b] . fc_w[c] + fc_b[c] ----------------
__global__ void fc_kernel(const float* __restrict__ fc_w, const float* __restrict__ fc_b,
                          float* __restrict__ out)
{
    int b = blockIdx.x, tid = threadIdx.x;  // 128 threads
    __shared__ float cs[HH];
    cs[tid] = g_ctx[b*HH + tid];
    __syncthreads();
    if (tid < NC) {
        float acc = fc_b[tid];
        for (int k = 0; k < HH; k++) acc += cs[k] * fc_w[tid*HH + k];
        out[b*NC + tid] = acc;
    }
}

// ---------------- launch ----------------
extern "C" void kernel_launch(void* const* d_in, const int* in_sizes, int n_in,
                              void* d_out, int out_size)
{
    (void)in_sizes; (void)n_in;
    const float* x        = (const float*)d_in[0];
    const float* Wih      = (const float*)d_in[1];
    const float* Whh      = (const float*)d_in[2];
    const float* bih      = (const float*)d_in[3];
    const float* bhh      = (const float*)d_in[4];
    const float* proj_h_w = (const float*)d_in[5];
    const float* proj_h_b = (const float*)d_in[6];
    const float* proj_x_w = (const float*)d_in[7];
    const float* proj_x_b = (const float*)d_in[8];
    const float* attn_w   = (const float*)d_in[9];
    const float* fc_w     = (const float*)d_in[10];
    const float* fc_b     = (const float*)d_in[11];

    float *p_x2, *p_gin, *p_bufA, *p_bufB, *p_ln, *p_ph, *p_px, *p_fc_s, *p_map_s;
    cudaGetSymbolAddress((void**)&p_x2,   g_x2);
    cudaGetSymbolAddress((void**)&p_gin,  g_gin);
    cudaGetSymbolAddress((void**)&p_bufA, g_bufA);
    cudaGetSymbolAddress((void**)&p_bufB, g_bufB);
    cudaGetSymbolAddress((void**)&p_ln,   g_ln);
    cudaGetSymbolAddress((void**)&p_ph,   g_ph);
    cudaGetSymbolAddress((void**)&p_px,   g_px);
    cudaGetSymbolAddress((void**)&p_fc_s, g_fc_scratch);
    cudaGetSymbolAddress((void**)&p_map_s, g_map_scratch);

    float* outf = (float*)d_out;
    float* out_fc;
    float* out_map;
    if (out_size >= BB*NC + BT*DD) { out_fc = outf;   out_map = outf + BB*NC; }
    else if (out_size == BT*DD)    { out_map = outf;  out_fc  = p_fc_s; }
    else                           { out_fc = outf;   out_map = p_map_s; }

    stats_kernel<<<DD, 256>>>(x);
    norm1_kernel<<<BB*DD, 256>>>(x);

    const float* cur = p_x2;
    for (int l = 0; l < LL; l++) {
        gemm16_kernel<<<BT/16, GG>>>(cur, Wih + (size_t)l*GG*DD,
                                     bih + l*GG, bhh + l*GG, p_gin, GG);
        float* nxt = (l & 1) ? p_bufB : p_bufA;
        lstm_rec_kernel<<<BB, GG>>>(p_gin, Whh + (size_t)l*GG*HH, nxt);
        cur = nxt;
    }

    instnorm_kernel<<<BB*HH, 256>>>(cur, p_ln, HH);
    gemm16_kernel<<<BT/16, HH>>>(p_ln, proj_h_w, proj_h_b, nullptr, p_ph, HH);
    gemm16_kernel<<<BT/16, HH>>>(p_x2, proj_x_w, proj_x_b, nullptr, p_gin, HH); // px raw into gin scratch
    instnorm_kernel<<<BB*HH, 256>>>(p_gin, p_px, HH);

    attn_s_kernel<<<BT, HH>>>(p_ph, p_px, attn_w);
    softmax_map_kernel<<<BB, TT>>>(out_map);
    context_kernel<<<BB, HH>>>(p_ph);
    fc_kernel<<<BB, HH>>>(fc_w, fc_b, out_fc);
}

// round 4
// speedup vs baseline: 1.8176x; 1.8176x over previous
#include <cuda_runtime.h>
#include <math.h>
#include <stdint.h>

#define BB 16
#define TT 256
#define DD 128
#define HH 128
#define LL 4
#define GG (4*HH)      // 512 gates
#define NC 10
#define EPSF 1e-5f
#define BT (BB*TT)     // 4096
#define CLU 4          // CTAs per batch element (cluster)

// ---------------- scratch (device globals; no allocation allowed) ----------------
__device__ float g_x2[BT*DD];      // normalized input
__device__ float g_gin[BT*GG];     // per-layer input-gemm result (reused)
__device__ float g_bufA[BT*HH];
__device__ float g_bufB[BT*HH];
__device__ float g_ln[BT*HH];      // instnorm(lstm_out)
__device__ float g_ph[BT*HH];
__device__ float g_px[BT*HH];
__device__ float g_mu[DD];
__device__ float g_sd[DD];
__device__ float g_s[BT];          // attention logits per (b,t)
__device__ float g_p[BT];          // softmax over t
__device__ float g_ctx[BB*HH];
__device__ float g_fc_scratch[BB*NC];
__device__ float g_map_scratch[BT*DD];

// ---------------- helpers ----------------
__device__ __forceinline__ float warpSum(float v) {
    #pragma unroll
    for (int o = 16; o > 0; o >>= 1) v += __shfl_xor_sync(0xffffffffu, v, o);
    return v;
}
__device__ __forceinline__ float sigf(float x) { return 1.0f / (1.0f + expf(-x)); }

// fast sigmoid: __expf (ex2.approx based) + fast divide
__device__ __forceinline__ float fsig(float x) {
    return __fdividef(1.0f, 1.0f + __expf(-x));
}

__device__ __forceinline__ unsigned int smem_u32(const void* p) {
    unsigned int a;
    asm("{ .reg .u64 t; cvta.to.shared.u64 t, %1; cvt.u32.u64 %0, t; }" : "=r"(a) : "l"(p));
    return a;
}
__device__ __forceinline__ unsigned int mapa_u32(unsigned int local, unsigned int rank) {
    unsigned int r;
    asm("mapa.shared::cluster.u32 %0, %1, %2;" : "=r"(r) : "r"(local), "r"(rank));
    return r;
}
__device__ __forceinline__ void fma2(unsigned long long& acc, unsigned long long a, unsigned long long b) {
    asm("fma.rn.f32x2 %0, %1, %2, %0;" : "+l"(acc) : "l"(a), "l"(b));
}
__device__ __forceinline__ void bar_wait_acq_cluster(unsigned int addr, int parity) {
    asm volatile(
        "{\n\t"
        ".reg .pred P;\n\t"
        "BWL_%=:\n\t"
        "mbarrier.try_wait.parity.acquire.cluster.shared::cta.b64 P, [%0], %1, 0x989680;\n\t"
        "@P bra BWD_%=;\n\t"
        "bra BWL_%=;\n\t"
        "BWD_%=:\n\t"
        "}"
        :: "r"(addr), "r"(parity) : "memory");
}

// ---------------- per-feature global mean / std (ddof=1), std+EPS ----------------
__global__ void stats_kernel(const float* __restrict__ x) {
    int d = blockIdx.x;
    float s = 0.f, s2 = 0.f;
    for (int i = threadIdx.x; i < BT; i += blockDim.x) {
        float v = x[i*DD + d];
        s += v; s2 += v*v;
    }
    __shared__ float sh[64];
    s = warpSum(s); s2 = warpSum(s2);
    int w = threadIdx.x >> 5, ln = threadIdx.x & 31;
    if (ln == 0) { sh[w] = s; sh[32+w] = s2; }
    __syncthreads();
    if (threadIdx.x == 0) {
        float S = 0.f, S2 = 0.f;
        int nw = blockDim.x >> 5;
        for (int i = 0; i < nw; i++) { S += sh[i]; S2 += sh[32+i]; }
        float m = S / (float)BT;
        float var = (S2 - (float)BT*m*m) / ((float)BT - 1.0f);
        g_mu[d] = m;
        g_sd[d] = sqrtf(var) + EPSF;   // EPS added to std (torch-style)
    }
}

// ---------------- global normalize + instance norm over T, fused ----------------
__global__ void norm1_kernel(const float* __restrict__ x) {
    int b = blockIdx.x / DD, d = blockIdx.x % DD;
    int t = threadIdx.x;                  // 256 threads == T
    float mu = g_mu[d], sd = g_sd[d];
    float v = x[((b*TT) + t)*DD + d];
    float x1 = (v - mu) / sd;
    __shared__ float sh[16];
    float s = warpSum(x1), s2 = warpSum(x1*x1);
    int w = t >> 5, ln = t & 31;
    if (ln == 0) { sh[w] = s; sh[8+w] = s2; }
    __syncthreads();
    __shared__ float mm, rs;
    if (t == 0) {
        float S = 0.f, S2 = 0.f;
        for (int i = 0; i < 8; i++) { S += sh[i]; S2 += sh[8+i]; }
        float m = S / (float)TT;
        float var = S2 / (float)TT - m*m;  // biased
        mm = m; rs = rsqrtf(var + EPSF);
    }
    __syncthreads();
    g_x2[((b*TT) + t)*DD + d] = (x1 - mm) * rs;
}

// ---------------- generic instance norm over T per (b,c) ----------------
__global__ void instnorm_kernel(const float* __restrict__ in, float* __restrict__ out, int C) {
    int b = blockIdx.x / C, c = blockIdx.x % C;
    int t = threadIdx.x;
    float v = in[((b*TT) + t)*C + c];
    __shared__ float sh[16];
    float s = warpSum(v), s2 = warpSum(v*v);
    int w = t >> 5, ln = t & 31;
    if (ln == 0) { sh[w] = s; sh[8+w] = s2; }
    __syncthreads();
    __shared__ float mm, rs;
    if (t == 0) {
        float S = 0.f, S2 = 0.f;
        for (int i = 0; i < 8; i++) { S += sh[i]; S2 += sh[8+i]; }
        float m = S / (float)TT;
        float var = S2 / (float)TT - m*m;
        mm = m; rs = rsqrtf(var + EPSF);
    }
    __syncthreads();
    out[((b*TT) + t)*C + c] = (v - mm) * rs;
}

// ---------------- C[m,j] = sum_k A[m,k]*W[j,k] + b1[j] (+ b2[j]); K=128 ----------------
__global__ void __launch_bounds__(512, 2) gemm16_kernel(
    const float* __restrict__ A, const float* __restrict__ W,
    const float* __restrict__ b1, const float* __restrict__ b2,
    float* __restrict__ C, int N)
{
    __shared__ __align__(16) float As[16*128];
    int m0 = blockIdx.x * 16;
    for (int idx = threadIdx.x; idx < 16*128; idx += blockDim.x)
        As[idx] = A[m0*128 + idx];
    __syncthreads();
    int j = threadIdx.x;
    float bias = b1[j] + (b2 ? b2[j] : 0.0f);
    float acc[16];
    #pragma unroll
    for (int mi = 0; mi < 16; mi++) acc[mi] = bias;
    const float4* W4 = reinterpret_cast<const float4*>(W) + j*32;
    for (int k4 = 0; k4 < 32; k4++) {
        float4 w = W4[k4];
        #pragma unroll
        for (int mi = 0; mi < 16; mi++) {
            float4 a = *reinterpret_cast<const float4*>(&As[mi*128 + k4*4]);
            acc[mi] += a.x*w.x + a.y*w.y + a.z*w.z + a.w*w.w;
        }
    }
    #pragma unroll
    for (int mi = 0; mi < 16; mi++) C[(m0+mi)*N + j] = acc[mi];
}

// ---------------- LSTM recurrence, register-resident weights, 4-CTA cluster per batch ----------
// CTA q of a cluster owns hidden units [32q, 32q+32) (128 gate rows).
// thread tid: row_local = tid>>2 (0..127), ks = tid&3 (k-quarter).
// Weights W[row][32ks..32ks+32) live in 16 packed f32x2 registers.
__global__ void __launch_bounds__(512, 1) __cluster_dims__(CLU, 1, 1)
lstm_rec_clu(const float* __restrict__ gin, const float* __restrict__ Whh,
             float* __restrict__ out)
{
    __shared__ __align__(16) float hbuf[2][HH];
    __shared__ float gates_s[128];
    __shared__ __align__(8) unsigned long long bar2[2];

    unsigned int rank;
    asm("mov.u32 %0, %%cluster_ctarank;" : "=r"(rank));
    int b = blockIdx.x >> 2;
    int tid = threadIdx.x;
    int row_local = tid >> 2;
    int ks = tid & 3;
    int gtype = row_local >> 5;
    int hu_l = row_local & 31;
    int row_g = gtype*HH + (int)rank*32 + hu_l;   // global gate row 0..511

    // load this thread's 32 weights as 16 f32x2 pairs
    unsigned long long w[16];
    const unsigned long long* Wp =
        reinterpret_cast<const unsigned long long*>(Whh + (size_t)row_g*HH + ks*32);
    #pragma unroll
    for (int i = 0; i < 16; i++) w[i] = Wp[i];

    if (tid < HH) hbuf[0][tid] = 0.0f;
    unsigned int barloc = smem_u32(&bar2[0]);
    if (tid == 0) {
        asm volatile("mbarrier.init.shared.b64 [%0], %1;" :: "r"(barloc),   "r"(128) : "memory");
        asm volatile("mbarrier.init.shared.b64 [%0], %1;" :: "r"(barloc+8), "r"(128) : "memory");
    }
    __syncthreads();
    asm volatile("barrier.cluster.arrive.aligned;" ::: "memory");
    asm volatile("barrier.cluster.wait.aligned;"   ::: "memory");

    // warp0 precomputes remote store/arrive addresses
    unsigned int r_h[2][4], r_b[2][4];
    float c = 0.0f;
    if (tid < 32) {
        unsigned int h0 = smem_u32(&hbuf[0][rank*32 + tid]);
        unsigned int h1 = smem_u32(&hbuf[1][rank*32 + tid]);
        #pragma unroll
        for (int r = 0; r < 4; r++) {
            r_h[0][r] = mapa_u32(h0, r);
            r_h[1][r] = mapa_u32(h1, r);
            r_b[0][r] = mapa_u32(barloc,   r);
            r_b[1][r] = mapa_u32(barloc+8, r);
        }
    }

    const float* ginb = gin + ((size_t)b*TT)*GG + row_g;
    float* outb = out + ((size_t)b*TT)*HH + rank*32;
    float gin_cur = __ldg(ginb);      // t = 0
    int p0 = 0, p1 = 0;

    #pragma unroll 1
    for (int t = 0; t < TT; t++) {
        int cb = t & 1;
        if (t > 0) {
            if (cb) { bar_wait_acq_cluster(barloc + 8, p1); p1 ^= 1; }
            else    { bar_wait_acq_cluster(barloc,     p0); p0 ^= 1; }
        }
        // prefetch next step's gin (independent of barrier)
        float gin_nxt = 0.0f;
        if (t + 1 < TT) gin_nxt = __ldg(ginb + (size_t)(t+1)*GG);

        // 32-MAC partial dot product via packed f32x2 FMA
        const uint4* h4 = reinterpret_cast<const uint4*>(&hbuf[cb][ks*32]);
        unsigned long long acc = 0ULL;
        #pragma unroll
        for (int i = 0; i < 8; i++) {
            uint4 hv = h4[i];
            unsigned long long hA = ((unsigned long long)hv.y << 32) | hv.x;
            unsigned long long hB = ((unsigned long long)hv.w << 32) | hv.z;
            fma2(acc, w[2*i],   hA);
            fma2(acc, w[2*i+1], hB);
        }
        float lo = __uint_as_float((unsigned)(acc & 0xffffffffULL));
        float hi = __uint_as_float((unsigned)(acc >> 32));
        float part = lo + hi;
        part += __shfl_xor_sync(0xffffffffu, part, 1);
        part += __shfl_xor_sync(0xffffffffu, part, 2);
        if (ks == 0) gates_s[row_local] = part + gin_cur;
        gin_cur = gin_nxt;
        __syncthreads();

        if (tid < 32) {
            float gi = gates_s[tid],      gf = gates_s[32+tid];
            float gg = gates_s[64+tid],   go = gates_s[96+tid];
            float si = fsig(gi), sf = fsig(gf), so = fsig(go);
            float tg = 2.0f*fsig(2.0f*gg) - 1.0f;     // tanh(gg)
            c = sf*c + si*tg;
            float tc = 2.0f*fsig(2.0f*c) - 1.0f;      // tanh(c)
            float hn = so*tc;
            outb[(size_t)t*HH + tid] = hn;
            if (t + 1 < TT) {
                int nb = (t + 1) & 1;
                #pragma unroll
                for (int r = 0; r < 4; r++)
                    asm volatile("st.shared::cluster.f32 [%0], %1;"
                                 :: "r"(r_h[nb][r]), "f"(hn) : "memory");
                #pragma unroll
                for (int r = 0; r < 4; r++)
                    asm volatile("mbarrier.arrive.release.cluster.shared::cluster.b64 _, [%0];"
                                 :: "r"(r_b[nb][r]) : "memory");
            }
        }
    }
    // no CTA may exit while peers might still address its SMEM
    asm volatile("barrier.cluster.arrive.aligned;" ::: "memory");
    asm volatile("barrier.cluster.wait.aligned;"   ::: "memory");
}

// ---------------- attention logit s[b,t] = sum_h tanh(ph+px)*aw[h] ----------------
__global__ void attn_s_kernel(const float* __restrict__ ph, const float* __restrict__ px,
                              const float* __restrict__ aw)
{
    int bt = blockIdx.x;
    int h = threadIdx.x;                 // 128
    float v = tanhf(ph[bt*HH + h] + px[bt*HH + h]) * aw[h];
    __shared__ float sh[4];
    v = warpSum(v);
    if ((h & 31) == 0) sh[h >> 5] = v;
    __syncthreads();
    if (h == 0) g_s[bt] = sh[0] + sh[1] + sh[2] + sh[3];
}

// ---------------- softmax over t (per b) + write attention map p_t/128 ----------------
__global__ void softmax_map_kernel(float* __restrict__ out_map) {
    int b = blockIdx.x, t = threadIdx.x;  // 256 threads
    float v = g_s[b*TT + t];
    __shared__ float sh[8];
    __shared__ float bc;
    float m = v;
    #pragma unroll
    for (int o = 16; o > 0; o >>= 1) m = fmaxf(m, __shfl_xor_sync(0xffffffffu, m, o));
    if ((t & 31) == 0) sh[t >> 5] = m;
    __syncthreads();
    if (t == 0) {
        float M = sh[0];
        for (int i = 1; i < 8; i++) M = fmaxf(M, sh[i]);
        bc = M;
    }
    __syncthreads();
    float M = bc;
    float e = expf(v - M);
    __syncthreads();
    float s = warpSum(e);
    if ((t & 31) == 0) sh[t >> 5] = s;
    __syncthreads();
    if (t == 0) {
        float S = 0.f;
        for (int i = 0; i < 8; i++) S += sh[i];
        bc = S;
    }
    __syncthreads();
    float p = e / bc;
    g_p[b*TT + t] = p;
    __shared__ float ps[TT];
    ps[t] = p * (1.0f / (float)DD);
    __syncthreads();
    const int base = b*TT*DD;
    for (int idx = t; idx < TT*DD; idx += TT)
        out_map[base + idx] = ps[idx >> 7];   // idx = t*128 + d
}

// ---------------- context[b,h] = sum_t ph[b,t,h] * p[b,t] ----------------
__global__ void context_kernel(const float* __restrict__ ph) {
    int b = blockIdx.x, h = threadIdx.x;   // 128 threads
    __shared__ float ps[TT];
    ps[h] = g_p[b*TT + h];
    ps[h + 128] = g_p[b*TT + h + 128];
    __syncthreads();
    float acc = 0.f;
    for (int t = 0; t < TT; t++)
        acc += ph[(b*TT + t)*HH + h] * ps[t];
    g_ctx[b*HH + h] = acc;
}

// ---------------- out[b,c] = ctx[b] . fc_w[c] + fc_b[c] ----------------
__global__ void fc_kernel(const float* __restrict__ fc_w, const float* __restrict__ fc_b,
                          float* __restrict__ out)
{
    int b = blockIdx.x, tid = threadIdx.x;  // 128 threads
    __shared__ float cs[HH];
    cs[tid] = g_ctx[b*HH + tid];
    __syncthreads();
    if (tid < NC) {
        float acc = fc_b[tid];
        for (int k = 0; k < HH; k++) acc += cs[k] * fc_w[tid*HH + k];
        out[b*NC + tid] = acc;
    }
}

// ---------------- launch ----------------
extern "C" void kernel_launch(void* const* d_in, const int* in_sizes, int n_in,
                              void* d_out, int out_size)
{
    (void)in_sizes; (void)n_in;
    const float* x        = (const float*)d_in[0];
    const float* Wih      = (const float*)d_in[1];
    const float* Whh      = (const float*)d_in[2];
    const float* bih      = (const float*)d_in[3];
    const float* bhh      = (const float*)d_in[4];
    const float* proj_h_w = (const float*)d_in[5];
    const float* proj_h_b = (const float*)d_in[6];
    const float* proj_x_w = (const float*)d_in[7];
    const float* proj_x_b = (const float*)d_in[8];
    const float* attn_w   = (const float*)d_in[9];
    const float* fc_w     = (const float*)d_in[10];
    const float* fc_b     = (const float*)d_in[11];

    float *p_x2, *p_gin, *p_bufA, *p_bufB, *p_ln, *p_ph, *p_px, *p_fc_s, *p_map_s;
    cudaGetSymbolAddress((void**)&p_x2,   g_x2);
    cudaGetSymbolAddress((void**)&p_gin,  g_gin);
    cudaGetSymbolAddress((void**)&p_bufA, g_bufA);
    cudaGetSymbolAddress((void**)&p_bufB, g_bufB);
    cudaGetSymbolAddress((void**)&p_ln,   g_ln);
    cudaGetSymbolAddress((void**)&p_ph,   g_ph);
    cudaGetSymbolAddress((void**)&p_px,   g_px);
    cudaGetSymbolAddress((void**)&p_fc_s, g_fc_scratch);
    cudaGetSymbolAddress((void**)&p_map_s, g_map_scratch);

    float* outf = (float*)d_out;
    float* out_fc;
    float* out_map;
    if (out_size >= BB*NC + BT*DD) { out_fc = outf;   out_map = outf + BB*NC; }
    else if (out_size == BT*DD)    { out_map = outf;  out_fc  = p_fc_s; }
    else                           { out_fc = outf;   out_map = p_map_s; }

    stats_kernel<<<DD, 256>>>(x);
    norm1_kernel<<<BB*DD, 256>>>(x);

    const float* cur = p_x2;
    for (int l = 0; l < LL; l++) {
        gemm16_kernel<<<BT/16, GG>>>(cur, Wih + (size_t)l*GG*DD,
                                     bih + l*GG, bhh + l*GG, p_gin, GG);
        float* nxt = (l & 1) ? p_bufB : p_bufA;
        lstm_rec_clu<<<BB*CLU, 512>>>(p_gin, Whh + (size_t)l*GG*HH, nxt);
        cur = nxt;
    }

    instnorm_kernel<<<BB*HH, 256>>>(cur, p_ln, HH);
    gemm16_kernel<<<BT/16, HH>>>(p_ln, proj_h_w, proj_h_b, nullptr, p_ph, HH);
    gemm16_kernel<<<BT/16, HH>>>(p_x2, proj_x_w, proj_x_b, nullptr, p_gin, HH);
    instnorm_kernel<<<BB*HH, 256>>>(p_gin, p_px, HH);

    attn_s_kernel<<<BT, HH>>>(p_ph, p_px, attn_w);
    softmax_map_kernel<<<BB, TT>>>(out_map);
    context_kernel<<<BB, HH>>>(p_ph);
    fc_kernel<<<BB, HH>>>(fc_w, fc_b, out_fc);
}

// round 6
// speedup vs baseline: 5.8384x; 3.2121x over previous
#include <cuda_runtime.h>
#include <math.h>
#include <stdint.h>

#define BB 16
#define TT 256
#define DD 128
#define HH 128
#define LL 4
#define GG (4*HH)      // 512 gates
#define NC 10
#define EPSF 1e-5f
#define BT (BB*TT)     // 4096
#define CC 32          // chunk length
#define KK (TT/CC)     // 8 chunks
#define NDIAG (LL+KK-1)

// ---------------- scratch (device globals; no allocation allowed) ----------------
__device__ float g_x2[BT*DD];
__device__ float g_gin[BT*GG];        // layer-0 input-gemm result (with biases)
__device__ float g_hall[LL*BT*HH];    // per-layer hidden outputs
__device__ float g_hstate[LL*BB*HH];  // chunk-boundary h
__device__ float g_cstate[LL*BB*HH];  // chunk-boundary c
__device__ float g_ln[BT*HH];
__device__ float g_ph[BT*HH];
__device__ float g_px[BT*HH];
__device__ float g_pxr[BT*HH];
__device__ float g_mu[DD];
__device__ float g_sd[DD];
__device__ float g_s[BT];
__device__ float g_p[BT];
__device__ float g_ctx[BB*HH];
__device__ float g_fc_scratch[BB*NC];
__device__ float g_map_scratch[BT*DD];

// ---------------- helpers ----------------
__device__ __forceinline__ float warpSum(float v) {
    #pragma unroll
    for (int o = 16; o > 0; o >>= 1) v += __shfl_xor_sync(0xffffffffu, v, o);
    return v;
}
__device__ __forceinline__ float fsig(float x) {
    return __fdividef(1.0f, 1.0f + __expf(-x));
}
__device__ __forceinline__ unsigned int smem_u32(const void* p) {
    unsigned int a;
    asm("{ .reg .u64 t; cvta.to.shared.u64 t, %1; cvt.u32.u64 %0, t; }" : "=r"(a) : "l"(p));
    return a;
}
__device__ __forceinline__ unsigned int mapa_u32(unsigned int local, unsigned int rank) {
    unsigned int r;
    asm("mapa.shared::cluster.u32 %0, %1, %2;" : "=r"(r) : "r"(local), "r"(rank));
    return r;
}
__device__ __forceinline__ void fma2(unsigned long long& acc, unsigned long long a, unsigned long long b) {
    asm("fma.rn.f32x2 %0, %1, %2, %0;" : "+l"(acc) : "l"(a), "l"(b));
}
__device__ __forceinline__ void mbar_init(unsigned int addr, unsigned int cnt) {
    asm volatile("mbarrier.init.shared.b64 [%0], %1;" :: "r"(addr), "r"(cnt) : "memory");
}
__device__ __forceinline__ void mbar_expect_tx(unsigned int addr, unsigned int bytes) {
    asm volatile("mbarrier.arrive.expect_tx.shared.b64 _, [%0], %1;" :: "r"(addr), "r"(bytes) : "memory");
}
__device__ __forceinline__ void st_async_f32(unsigned int addr, float v, unsigned int mbar) {
    asm volatile("st.async.shared::cluster.mbarrier::complete_tx::bytes.b32 [%0], %1, [%2];"
                 :: "r"(addr), "r"(__float_as_uint(v)), "r"(mbar) : "memory");
}
__device__ __forceinline__ void bar_wait_acq_cluster(unsigned int addr, int parity) {
    asm volatile(
        "{\n\t"
        ".reg .pred P;\n\t"
        "BWL_%=:\n\t"
        "mbarrier.try_wait.parity.acquire.cluster.shared::cta.b64 P, [%0], %1, 0x989680;\n\t"
        "@P bra BWD_%=;\n\t"
        "bra BWL_%=;\n\t"
        "BWD_%=:\n\t"
        "}"
        :: "r"(addr), "r"(parity) : "memory");
}

// ---------------- per-feature global mean / std (ddof=1), std+EPS ----------------
__global__ void stats_kernel(const float* __restrict__ x) {
    int d = blockIdx.x;
    float s = 0.f, s2 = 0.f;
    for (int i = threadIdx.x; i < BT; i += blockDim.x) {
        float v = x[i*DD + d];
        s += v; s2 += v*v;
    }
    __shared__ float sh[64];
    s = warpSum(s); s2 = warpSum(s2);
    int w = threadIdx.x >> 5, ln = threadIdx.x & 31;
    if (ln == 0) { sh[w] = s; sh[32+w] = s2; }
    __syncthreads();
    if (threadIdx.x == 0) {
        float S = 0.f, S2 = 0.f;
        int nw = blockDim.x >> 5;
        for (int i = 0; i < nw; i++) { S += sh[i]; S2 += sh[32+i]; }
        float m = S / (float)BT;
        float var = (S2 - (float)BT*m*m) / ((float)BT - 1.0f);
        g_mu[d] = m;
        g_sd[d] = sqrtf(var) + EPSF;
    }
}

// ---------------- global normalize + instance norm over T, fused ----------------
__global__ void norm1_kernel(const float* __restrict__ x) {
    int b = blockIdx.x / DD, d = blockIdx.x % DD;
    int t = threadIdx.x;
    float mu = g_mu[d], sd = g_sd[d];
    float v = x[((b*TT) + t)*DD + d];
    float x1 = (v - mu) / sd;
    __shared__ float sh[16];
    float s = warpSum(x1), s2 = warpSum(x1*x1);
    int w = t >> 5, ln = t & 31;
    if (ln == 0) { sh[w] = s; sh[8+w] = s2; }
    __syncthreads();
    __shared__ float mm, rs;
    if (t == 0) {
        float S = 0.f, S2 = 0.f;
        for (int i = 0; i < 8; i++) { S += sh[i]; S2 += sh[8+i]; }
        float m = S / (float)TT;
        float var = S2 / (float)TT - m*m;
        mm = m; rs = rsqrtf(var + EPSF);
    }
    __syncthreads();
    g_x2[((b*TT) + t)*DD + d] = (x1 - mm) * rs;
}

// ---------------- generic instance norm over T per (b,c) ----------------
__global__ void instnorm_kernel(const float* __restrict__ in, float* __restrict__ out, int C) {
    int b = blockIdx.x / C, c = blockIdx.x % C;
    int t = threadIdx.x;
    float v = in[((b*TT) + t)*C + c];
    __shared__ float sh[16];
    float s = warpSum(v), s2 = warpSum(v*v);
    int w = t >> 5, ln = t & 31;
    if (ln == 0) { sh[w] = s; sh[8+w] = s2; }
    __syncthreads();
    __shared__ float mm, rs;
    if (t == 0) {
        float S = 0.f, S2 = 0.f;
        for (int i = 0; i < 8; i++) { S += sh[i]; S2 += sh[8+i]; }
        float m = S / (float)TT;
        float var = S2 / (float)TT - m*m;
        mm = m; rs = rsqrtf(var + EPSF);
    }
    __syncthreads();
    out[((b*TT) + t)*C + c] = (v - mm) * rs;
}

// ---------------- C[m,j] = sum_k A[m,k]*W[j,k] + b1[j] (+ b2[j]); K=128 ----------------
__global__ void __launch_bounds__(512, 2) gemm16_kernel(
    const float* __restrict__ A, const float* __restrict__ W,
    const float* __restrict__ b1, const float* __restrict__ b2,
    float* __restrict__ C, int N)
{
    __shared__ __align__(16) float As[16*128];
    int m0 = blockIdx.x * 16;
    for (int idx = threadIdx.x; idx < 16*128; idx += blockDim.x)
        As[idx] = A[m0*128 + idx];
    __syncthreads();
    int j = threadIdx.x;
    float bias = b1[j] + (b2 ? b2[j] : 0.0f);
    float acc[16];
    #pragma unroll
    for (int mi = 0; mi < 16; mi++) acc[mi] = bias;
    const float4* W4 = reinterpret_cast<const float4*>(W) + j*32;
    for (int k4 = 0; k4 < 32; k4++) {
        float4 w = W4[k4];
        #pragma unroll
        for (int mi = 0; mi < 16; mi++) {
            float4 a = *reinterpret_cast<const float4*>(&As[mi*128 + k4*4]);
            acc[mi] += a.x*w.x + a.y*w.y + a.z*w.z + a.w*w.w;
        }
    }
    #pragma unroll
    for (int mi = 0; mi < 16; mi++) C[(m0+mi)*N + j] = acc[mi];
}

// ==================== chunked wavefront LSTM cell kernel ====================
// One diagonal d: cells (l, k=d-l). Per cell: 16 batches x 2-CTA cluster.
// CTA q owns hidden units [64q, 64q+64) = 256 gate rows.
// Thread t: local row r = t>>1 (0..255), half = t&1 (k-halves of the 128-dot).
// Phase A: gin_s[s][r] = Wih.h_in(s) + bias (l>0) or copy of precomputed g_gin (l=0).
// Phase B: C recurrence steps; h exchanged between the 2 CTAs via st.async+tx.
__global__ void __launch_bounds__(512, 1) __cluster_dims__(2, 1, 1)
lstm_wave(int lmin, int d,
          const float* __restrict__ gin0,
          const float* __restrict__ Wih, const float* __restrict__ Whh,
          const float* __restrict__ bih, const float* __restrict__ bhh,
          float* __restrict__ hall, float* __restrict__ hstate, float* __restrict__ cstate)
{
    extern __shared__ float dyn[];
    float* gin_s = dyn;                // CC*256 floats
    float* hin_s = dyn + CC*256;       // CC*128 floats (l>0 only)
    __shared__ __align__(16) float hbuf[2][HH];
    __shared__ float gates_s[256];
    __shared__ __align__(8) unsigned long long barF[2];

    const int cell = blockIdx.x >> 5;          // 32 CTAs per cell
    const int b    = (blockIdx.x >> 1) & 15;
    const int q    = blockIdx.x & 1;
    const int l    = lmin + cell;
    const int k    = d - l;
    const int tid  = threadIdx.x;
    const int r    = tid >> 1;
    const int half = tid & 1;
    const int row_g = (r >> 6)*HH + q*64 + (r & 63);

    unsigned long long w[32];   // 64 weight floats, reused for Wih then Whh

    // ---------- Phase A: gin_s ----------
    if (l == 0) {
        const float* src = gin0 + ((size_t)(b*TT + k*CC))*GG;
        for (int idx = tid; idx < CC*256; idx += 512) {
            int s = idx >> 8, rr = idx & 255;
            int rg = (rr >> 6)*HH + q*64 + (rr & 63);
            gin_s[idx] = src[(size_t)s*GG + rg];
        }
    } else {
        const float* hsrc = hall + ((size_t)(l-1)*BT + b*TT + k*CC)*HH;
        for (int idx = tid; idx < CC*HH; idx += 512) hin_s[idx] = hsrc[idx];
        const unsigned long long* Wp =
            reinterpret_cast<const unsigned long long*>(Wih + ((size_t)l*GG + row_g)*HH + half*64);
        #pragma unroll
        for (int i = 0; i < 32; i++) w[i] = Wp[i];
        float bias = bih[l*GG + row_g] + bhh[l*GG + row_g];
        __syncthreads();
        for (int s = 0; s < CC; s++) {
            const ulonglong2* H = reinterpret_cast<const ulonglong2*>(&hin_s[s*HH + half*64]);
            unsigned long long a0 = 0ULL, a1 = 0ULL;
            #pragma unroll
            for (int i = 0; i < 8; i++) {
                ulonglong2 h2 = H[2*i], h3 = H[2*i+1];
                fma2(a0, w[4*i],   h2.x); fma2(a1, w[4*i+1], h2.y);
                fma2(a0, w[4*i+2], h3.x); fma2(a1, w[4*i+3], h3.y);
            }
            float part = __uint_as_float((unsigned)(a0 & 0xffffffffULL))
                       + __uint_as_float((unsigned)(a0 >> 32))
                       + __uint_as_float((unsigned)(a1 & 0xffffffffULL))
                       + __uint_as_float((unsigned)(a1 >> 32));
            part += __shfl_xor_sync(0xffffffffu, part, 1);
            if (half == 0) gin_s[s*256 + r] = part + bias;
        }
    }

    // ---------- Phase B setup ----------
    {
        const unsigned long long* Wp =
            reinterpret_cast<const unsigned long long*>(Whh + ((size_t)l*GG + row_g)*HH + half*64);
        #pragma unroll
        for (int i = 0; i < 32; i++) w[i] = Wp[i];
    }
    const int sidx = (l*BB + b)*HH;
    if (tid < HH) hbuf[0][tid] = (k == 0) ? 0.f : hstate[sidx + tid];
    float c = 0.f;
    if (tid < 64 && k > 0) c = cstate[sidx + q*64 + tid];

    const unsigned int barF_loc = smem_u32(&barF[0]);
    if (tid == 0) {
        mbar_init(barF_loc,     1);
        mbar_init(barF_loc + 8, 1);
        mbar_expect_tx(barF_loc + 8, 512u);   // h(0) -> slot 1
        mbar_expect_tx(barF_loc,     512u);   // h(1) -> slot 0
    }
    unsigned int dstH[2][2], dstB[2][2];
    if (tid < 64) {
        unsigned int h0 = smem_u32(&hbuf[0][q*64 + tid]);
        unsigned int h1 = smem_u32(&hbuf[1][q*64 + tid]);
        #pragma unroll
        for (int rk = 0; rk < 2; rk++) {
            dstH[0][rk] = mapa_u32(h0, rk);
            dstH[1][rk] = mapa_u32(h1, rk);
            dstB[0][rk] = mapa_u32(barF_loc,     rk);
            dstB[1][rk] = mapa_u32(barF_loc + 8, rk);
        }
    }
    __syncthreads();
    asm volatile("barrier.cluster.arrive.aligned;" ::: "memory");
    asm volatile("barrier.cluster.wait.aligned;"   ::: "memory");

    float* hout = hall + ((size_t)l*BT + b*TT + k*CC)*HH + q*64;
    int pF[2] = {0, 0};

    // ---------- Phase B: C recurrence steps ----------
    #pragma unroll 1
    for (int s = 0; s < CC; s++) {
        const int sl = s & 1;
        if (s >= 1) {
            bar_wait_acq_cluster(barF_loc + 8*sl, pF[sl]); pF[sl] ^= 1;
            if (tid == 0 && (s + 1) <= CC - 2) mbar_expect_tx(barF_loc + 8*sl, 512u);
        }
        const ulonglong2* H = reinterpret_cast<const ulonglong2*>(&hbuf[sl][half*64]);
        unsigned long long a0 = 0ULL, a1 = 0ULL;
        #pragma unroll
        for (int i = 0; i < 8; i++) {
            ulonglong2 h2 = H[2*i], h3 = H[2*i+1];
            fma2(a0, w[4*i],   h2.x); fma2(a1, w[4*i+1], h2.y);
            fma2(a0, w[4*i+2], h3.x); fma2(a1, w[4*i+3], h3.y);
        }
        float part = __uint_as_float((unsigned)(a0 & 0xffffffffULL))
                   + __uint_as_float((unsigned)(a0 >> 32))
                   + __uint_as_float((unsigned)(a1 & 0xffffffffULL))
                   + __uint_as_float((unsigned)(a1 >> 32));
        part += __shfl_xor_sync(0xffffffffu, part, 1);
        if (half == 0) gates_s[r] = part + gin_s[s*256 + r];
        __syncthreads();

        if (tid < 64) {
            float gi = gates_s[tid],       gf = gates_s[64 + tid];
            float gg = gates_s[128 + tid], go = gates_s[192 + tid];
            float si = fsig(gi), sf = fsig(gf), so = fsig(go);
            float tg = 2.0f*fsig(2.0f*gg) - 1.0f;
            c = sf*c + si*tg;
            float tc = 2.0f*fsig(2.0f*c) - 1.0f;
            float hn = so*tc;
            hout[(size_t)s*HH + tid] = hn;
            if (s <= CC - 2) {
                int ns = (s + 1) & 1;
                st_async_f32(dstH[ns][0], hn, dstB[ns][0]);
                st_async_f32(dstH[ns][1], hn, dstB[ns][1]);
            } else {
                hstate[sidx + q*64 + tid] = hn;
                cstate[sidx + q*64 + tid] = c;
            }
        }
    }
    asm volatile("barrier.cluster.arrive.aligned;" ::: "memory");
    asm volatile("barrier.cluster.wait.aligned;"   ::: "memory");
}

// ---------------- attention logit s[b,t] = sum_h tanh(ph+px)*aw[h] ----------------
__global__ void attn_s_kernel(const float* __restrict__ ph, const float* __restrict__ px,
                              const float* __restrict__ aw)
{
    int bt = blockIdx.x;
    int h = threadIdx.x;
    float v = tanhf(ph[bt*HH + h] + px[bt*HH + h]) * aw[h];
    __shared__ float sh[4];
    v = warpSum(v);
    if ((h & 31) == 0) sh[h >> 5] = v;
    __syncthreads();
    if (h == 0) g_s[bt] = sh[0] + sh[1] + sh[2] + sh[3];
}

// ---------------- softmax over t (per b) + attention map p_t/128 ----------------
__global__ void softmax_map_kernel(float* __restrict__ out_map) {
    int b = blockIdx.x, t = threadIdx.x;
    float v = g_s[b*TT + t];
    __shared__ float sh[8];
    __shared__ float bc;
    float m = v;
    #pragma unroll
    for (int o = 16; o > 0; o >>= 1) m = fmaxf(m, __shfl_xor_sync(0xffffffffu, m, o));
    if ((t & 31) == 0) sh[t >> 5] = m;
    __syncthreads();
    if (t == 0) {
        float M = sh[0];
        for (int i = 1; i < 8; i++) M = fmaxf(M, sh[i]);
        bc = M;
    }
    __syncthreads();
    float M = bc;
    float e = expf(v - M);
    __syncthreads();
    float s = warpSum(e);
    if ((t & 31) == 0) sh[t >> 5] = s;
    __syncthreads();
    if (t == 0) {
        float S = 0.f;
        for (int i = 0; i < 8; i++) S += sh[i];
        bc = S;
    }
    __syncthreads();
    float pp = e / bc;
    g_p[b*TT + t] = pp;
    __shared__ float ps[TT];
    ps[t] = pp * (1.0f / (float)DD);
    __syncthreads();
    const int base = b*TT*DD;
    for (int idx = t; idx < TT*DD; idx += TT)
        out_map[base + idx] = ps[idx >> 7];
}

// ---------------- context[b,h] = sum_t ph[b,t,h] * p[b,t] ----------------
__global__ void context_kernel(const float* __restrict__ ph) {
    int b = blockIdx.x, h = threadIdx.x;
    __shared__ float ps[TT];
    ps[h] = g_p[b*TT + h];
    ps[h + 128] = g_p[b*TT + h + 128];
    __syncthreads();
    float acc = 0.f;
    for (int t = 0; t < TT; t++)
        acc += ph[(b*TT + t)*HH + h] * ps[t];
    g_ctx[b*HH + h] = acc;
}

// ---------------- out[b,c] = ctx[b] . fc_w[c] + fc_b[c] ----------------
__global__ void fc_kernel(const float* __restrict__ fc_w, const float* __restrict__ fc_b,
                          float* __restrict__ out)
{
    int b = blockIdx.x, tid = threadIdx.x;
    __shared__ float cs[HH];
    cs[tid] = g_ctx[b*HH + tid];
    __syncthreads();
    if (tid < NC) {
        float acc = fc_b[tid];
        for (int k = 0; k < HH; k++) acc += cs[k] * fc_w[tid*HH + k];
        out[b*NC + tid] = acc;
    }
}

// ---------------- launch ----------------
extern "C" void kernel_launch(void* const* d_in, const int* in_sizes, int n_in,
                              void* d_out, int out_size)
{
    (void)in_sizes; (void)n_in;
    const float* x        = (const float*)d_in[0];
    const float* Wih      = (const float*)d_in[1];
    const float* Whh      = (const float*)d_in[2];
    const float* bih      = (const float*)d_in[3];
    const float* bhh      = (const float*)d_in[4];
    const float* proj_h_w = (const float*)d_in[5];
    const float* proj_h_b = (const float*)d_in[6];
    const float* proj_x_w = (const float*)d_in[7];
    const float* proj_x_b = (const float*)d_in[8];
    const float* attn_w   = (const float*)d_in[9];
    const float* fc_w     = (const float*)d_in[10];
    const float* fc_b     = (const float*)d_in[11];

    float *p_x2, *p_gin, *p_hall, *p_hst, *p_cst, *p_ln, *p_ph, *p_px, *p_pxr, *p_fc_s, *p_map_s;
    cudaGetSymbolAddress((void**)&p_x2,   g_x2);
    cudaGetSymbolAddress((void**)&p_gin,  g_gin);
    cudaGetSymbolAddress((void**)&p_hall, g_hall);
    cudaGetSymbolAddress((void**)&p_hst,  g_hstate);
    cudaGetSymbolAddress((void**)&p_cst,  g_cstate);
    cudaGetSymbolAddress((void**)&p_ln,   g_ln);
    cudaGetSymbolAddress((void**)&p_ph,   g_ph);
    cudaGetSymbolAddress((void**)&p_px,   g_px);
    cudaGetSymbolAddress((void**)&p_pxr,  g_pxr);
    cudaGetSymbolAddress((void**)&p_fc_s, g_fc_scratch);
    cudaGetSymbolAddress((void**)&p_map_s, g_map_scratch);

    float* outf = (float*)d_out;
    float* out_fc;
    float* out_map;
    if (out_size >= BB*NC + BT*DD) { out_fc = outf;   out_map = outf + BB*NC; }
    else if (out_size == BT*DD)    { out_map = outf;  out_fc  = p_fc_s; }
    else                           { out_fc = outf;   out_map = p_map_s; }

    const int dynSmem = (CC*256 + CC*128) * 4;   // 49152 bytes
    cudaFuncSetAttribute(lstm_wave, cudaFuncAttributeMaxDynamicSharedMemorySize, dynSmem);

    stats_kernel<<<DD, 256>>>(x);
    norm1_kernel<<<BB*DD, 256>>>(x);

    // layer-0 input GEMM (with biases); layers 1-3 input transforms run in-wave
    gemm16_kernel<<<BT/16, GG>>>(p_x2, Wih, bih, bhh, p_gin, GG);

    for (int d = 0; d < NDIAG; d++) {
        int lmin = (d - (KK - 1) > 0) ? d - (KK - 1) : 0;
        int lmax = (d < LL - 1) ? d : LL - 1;
        int ncells = lmax - lmin + 1;
        lstm_wave<<<ncells*BB*2, 512, dynSmem>>>(lmin, d, p_gin, Wih, Whh, bih, bhh,
                                                 p_hall, p_hst, p_cst);
    }

    const float* lstm_out = p_hall + (size_t)3*BT*HH;
    instnorm_kernel<<<BB*HH, 256>>>(lstm_out, p_ln, HH);
    gemm16_kernel<<<BT/16, HH>>>(p_ln, proj_h_w, proj_h_b, nullptr, p_ph, HH);
    gemm16_kernel<<<BT/16, HH>>>(p_x2, proj_x_w, proj_x_b, nullptr, p_pxr, HH);
    instnorm_kernel<<<BB*HH, 256>>>(p_pxr, p_px, HH);

    attn_s_kernel<<<BT, HH>>>(p_ph, p_px, attn_w);
    softmax_map_kernel<<<BB, TT>>>(out_map);
    context_kernel<<<BB, HH>>>(p_ph);
    fc_kernel<<<BB, HH>>>(fc_w, fc_b, out_fc);
}

// round 7
// speedup vs baseline: 7.2749x; 1.2460x over previous
#include <cuda_runtime.h>
#include <math.h>
#include <stdint.h>

#define BB 16
#define TT 256
#define DD 128
#define HH 128
#define LL 4
#define GG (4*HH)      // 512 gates
#define NC 10
#define EPSF 1e-5f
#define BT (BB*TT)     // 4096
#define CC 32          // chunk length
#define KK (TT/CC)     // 8 chunks
#define NDIAG (LL+KK-1)

// ---------------- scratch (device globals; no allocation allowed) ----------------
__device__ float g_x2[BT*DD];
__device__ float g_gin[BT*GG];        // layer-0 input-gemm result (with biases)
__device__ float g_hall[LL*BT*HH];    // per-layer hidden outputs
__device__ float g_hstate[LL*BB*HH];  // chunk-boundary h
__device__ float g_cstate[LL*BB*HH];  // chunk-boundary c
__device__ float g_ln[BT*HH];
__device__ float g_ph[BT*HH];
__device__ float g_px[BT*HH];
__device__ float g_pxr[BT*HH];
__device__ float g_mu[DD];
__device__ float g_sd[DD];
__device__ float g_ctx[BB*HH];
__device__ float g_fc_scratch[BB*NC];
__device__ float g_map_scratch[BT*DD];

// ---------------- helpers ----------------
__device__ __forceinline__ float warpSum(float v) {
    #pragma unroll
    for (int o = 16; o > 0; o >>= 1) v += __shfl_xor_sync(0xffffffffu, v, o);
    return v;
}
__device__ __forceinline__ float fsig(float x) {
    return __fdividef(1.0f, 1.0f + __expf(-x));
}
__device__ __forceinline__ unsigned int smem_u32(const void* p) {
    unsigned int a;
    asm("{ .reg .u64 t; cvta.to.shared.u64 t, %1; cvt.u32.u64 %0, t; }" : "=r"(a) : "l"(p));
    return a;
}
__device__ __forceinline__ unsigned int mapa_u32(unsigned int local, unsigned int rank) {
    unsigned int r;
    asm("mapa.shared::cluster.u32 %0, %1, %2;" : "=r"(r) : "r"(local), "r"(rank));
    return r;
}
__device__ __forceinline__ void fma2(unsigned long long& acc, unsigned long long a, unsigned long long b) {
    asm("fma.rn.f32x2 %0, %1, %2, %0;" : "+l"(acc) : "l"(a), "l"(b));
}
__device__ __forceinline__ void mbar_init(unsigned int addr, unsigned int cnt) {
    asm volatile("mbarrier.init.shared.b64 [%0], %1;" :: "r"(addr), "r"(cnt) : "memory");
}
__device__ __forceinline__ void mbar_expect_tx(unsigned int addr, unsigned int bytes) {
    asm volatile("mbarrier.arrive.expect_tx.shared.b64 _, [%0], %1;" :: "r"(addr), "r"(bytes) : "memory");
}
__device__ __forceinline__ void st_async_f32(unsigned int addr, float v, unsigned int mbar) {
    asm volatile("st.async.shared::cluster.mbarrier::complete_tx::bytes.b32 [%0], %1, [%2];"
                 :: "r"(addr), "r"(__float_as_uint(v)), "r"(mbar) : "memory");
}
__device__ __forceinline__ void bar_wait_acq_cluster(unsigned int addr, int parity) {
    asm volatile(
        "{\n\t"
        ".reg .pred P;\n\t"
        "BWL_%=:\n\t"
        "mbarrier.try_wait.parity.acquire.cluster.shared::cta.b64 P, [%0], %1, 0x989680;\n\t"
        "@P bra BWD_%=;\n\t"
        "bra BWL_%=;\n\t"
        "BWD_%=:\n\t"
        "}"
        :: "r"(addr), "r"(parity) : "memory");
}

// ---------------- per-feature global mean / std (ddof=1), std+EPS ----------------
__global__ void stats_kernel(const float* __restrict__ x) {
    int d = blockIdx.x;
    float s = 0.f, s2 = 0.f;
    for (int i = threadIdx.x; i < BT; i += blockDim.x) {
        float v = x[i*DD + d];
        s += v; s2 += v*v;
    }
    __shared__ float sh[64];
    s = warpSum(s); s2 = warpSum(s2);
    int w = threadIdx.x >> 5, ln = threadIdx.x & 31;
    if (ln == 0) { sh[w] = s; sh[32+w] = s2; }
    __syncthreads();
    if (threadIdx.x == 0) {
        float S = 0.f, S2 = 0.f;
        int nw = blockDim.x >> 5;
        for (int i = 0; i < nw; i++) { S += sh[i]; S2 += sh[32+i]; }
        float m = S / (float)BT;
        float var = (S2 - (float)BT*m*m) / ((float)BT - 1.0f);
        g_mu[d] = m;
        g_sd[d] = sqrtf(var) + EPSF;
    }
}

// ---------------- global normalize + instance norm over T, fused ----------------
__global__ void norm1_kernel(const float* __restrict__ x) {
    int b = blockIdx.x / DD, d = blockIdx.x % DD;
    int t = threadIdx.x;
    float mu = g_mu[d], sd = g_sd[d];
    float v = x[((b*TT) + t)*DD + d];
    float x1 = (v - mu) / sd;
    __shared__ float sh[16];
    float s = warpSum(x1), s2 = warpSum(x1*x1);
    int w = t >> 5, ln = t & 31;
    if (ln == 0) { sh[w] = s; sh[8+w] = s2; }
    __syncthreads();
    __shared__ float mm, rs;
    if (t == 0) {
        float S = 0.f, S2 = 0.f;
        for (int i = 0; i < 8; i++) { S += sh[i]; S2 += sh[8+i]; }
        float m = S / (float)TT;
        float var = S2 / (float)TT - m*m;
        mm = m; rs = rsqrtf(var + EPSF);
    }
    __syncthreads();
    g_x2[((b*TT) + t)*DD + d] = (x1 - mm) * rs;
}

// ---------------- generic instance norm over T per (b,c) ----------------
__global__ void instnorm_kernel(const float* __restrict__ in, float* __restrict__ out, int C) {
    int b = blockIdx.x / C, c = blockIdx.x % C;
    int t = threadIdx.x;
    float v = in[((b*TT) + t)*C + c];
    __shared__ float sh[16];
    float s = warpSum(v), s2 = warpSum(v*v);
    int w = t >> 5, ln = t & 31;
    if (ln == 0) { sh[w] = s; sh[8+w] = s2; }
    __syncthreads();
    __shared__ float mm, rs;
    if (t == 0) {
        float S = 0.f, S2 = 0.f;
        for (int i = 0; i < 8; i++) { S += sh[i]; S2 += sh[8+i]; }
        float m = S / (float)TT;
        float var = S2 / (float)TT - m*m;
        mm = m; rs = rsqrtf(var + EPSF);
    }
    __syncthreads();
    out[((b*TT) + t)*C + c] = (v - mm) * rs;
}

// ---------------- C[m,j] = sum_k A[m,k]*W[j,k] + b1[j] (+ b2[j]); K=128 ----------------
__global__ void __launch_bounds__(512, 2) gemm16_kernel(
    const float* __restrict__ A, const float* __restrict__ W,
    const float* __restrict__ b1, const float* __restrict__ b2,
    float* __restrict__ C, int N)
{
    __shared__ __align__(16) float As[16*128];
    int m0 = blockIdx.x * 16;
    for (int idx = threadIdx.x; idx < 16*128; idx += blockDim.x)
        As[idx] = A[m0*128 + idx];
    __syncthreads();
    int j = threadIdx.x;
    float bias = b1[j] + (b2 ? b2[j] : 0.0f);
    float acc[16];
    #pragma unroll
    for (int mi = 0; mi < 16; mi++) acc[mi] = bias;
    const float4* W4 = reinterpret_cast<const float4*>(W) + j*32;
    for (int k4 = 0; k4 < 32; k4++) {
        float4 w = W4[k4];
        #pragma unroll
        for (int mi = 0; mi < 16; mi++) {
            float4 a = *reinterpret_cast<const float4*>(&As[mi*128 + k4*4]);
            acc[mi] += a.x*w.x + a.y*w.y + a.z*w.z + a.w*w.w;
        }
    }
    #pragma unroll
    for (int mi = 0; mi < 16; mi++) C[(m0+mi)*N + j] = acc[mi];
}

// ==================== chunked wavefront LSTM, full-row-per-thread ====================
// One diagonal d: cells (l, k=d-l). Per cell: 16 batches x 2-CTA cluster.
// CTA q owns hidden units [64q, 64q+64) = 256 gate rows; 256 threads, one full
// 128-weight row per thread (registers). h exchange: own 64 via STS+sync,
// remote 64 via st.async + 256B tx barrier.
__global__ void __launch_bounds__(256, 1) __cluster_dims__(2, 1, 1)
lstm_wave(int lmin, int d,
          const float* __restrict__ gin0,
          const float* __restrict__ Wih, const float* __restrict__ Whh,
          const float* __restrict__ bih, const float* __restrict__ bhh,
          float* __restrict__ hall, float* __restrict__ hstate, float* __restrict__ cstate)
{
    extern __shared__ float dyn[];
    float* gin_s = dyn;                // CC*256
    float* hin_s = dyn + CC*256;       // CC*128 (l>0)
    __shared__ __align__(16) float hbuf[2][HH];
    __shared__ float gates_s[256];
    __shared__ __align__(8) unsigned long long barF[2];

    const int cell = blockIdx.x >> 5;          // 32 CTAs per cell
    const int b    = (blockIdx.x >> 1) & 15;
    const int q    = blockIdx.x & 1;
    const int l    = lmin + cell;
    const int k    = d - l;
    const int tid  = threadIdx.x;
    const int gtype = tid >> 6, u = tid & 63;
    const int row_g = gtype*HH + q*64 + u;

    unsigned long long w[64];   // full 128-weight row; Wih (phase A) then Whh (phase B)

    // ---------- Phase A: gin_s[s][tid] ----------
    if (l == 0) {
        const float* src = gin0 + ((size_t)(b*TT + k*CC))*GG + row_g;
        #pragma unroll 4
        for (int s = 0; s < CC; s++)
            gin_s[s*256 + tid] = src[(size_t)s*GG];
    } else {
        const float* hsrc = hall + ((size_t)(l-1)*BT + b*TT + k*CC)*HH;
        for (int idx = tid; idx < CC*HH; idx += 256) hin_s[idx] = hsrc[idx];
        {
            const unsigned long long* Wp =
                reinterpret_cast<const unsigned long long*>(Wih + ((size_t)l*GG + row_g)*HH);
            #pragma unroll
            for (int i = 0; i < 64; i++) w[i] = Wp[i];
        }
        float bias = bih[l*GG + row_g] + bhh[l*GG + row_g];
        __syncthreads();
        #pragma unroll 1
        for (int s = 0; s < CC; s++) {
            const ulonglong2* H = reinterpret_cast<const ulonglong2*>(&hin_s[s*HH]);
            unsigned long long a0 = 0ULL, a1 = 0ULL;
            #pragma unroll
            for (int i = 0; i < 32; i++) {
                ulonglong2 h2 = H[i];
                fma2(a0, w[2*i],   h2.x);
                fma2(a1, w[2*i+1], h2.y);
            }
            gin_s[s*256 + tid] = bias
                + __uint_as_float((unsigned)(a0 & 0xffffffffULL))
                + __uint_as_float((unsigned)(a0 >> 32))
                + __uint_as_float((unsigned)(a1 & 0xffffffffULL))
                + __uint_as_float((unsigned)(a1 >> 32));
        }
    }

    // ---------- Phase B setup ----------
    {
        const unsigned long long* Wp =
            reinterpret_cast<const unsigned long long*>(Whh + ((size_t)l*GG + row_g)*HH);
        #pragma unroll
        for (int i = 0; i < 64; i++) w[i] = Wp[i];
    }
    const int sidx = (l*BB + b)*HH;
    if (tid < HH) hbuf[0][tid] = (k == 0) ? 0.f : hstate[sidx + tid];
    float c = 0.f;
    if (tid < 64 && k > 0) c = cstate[sidx + q*64 + tid];

    const unsigned int barF_loc = smem_u32(&barF[0]);
    if (tid == 0) {
        mbar_init(barF_loc,     1);
        mbar_init(barF_loc + 8, 1);
    }
    __syncthreads();                     // barriers initialized before arming
    if (tid == 64) {
        mbar_expect_tx(barF_loc + 8, 256u);   // step 1 (slot 1)
        mbar_expect_tx(barF_loc,     256u);   // step 2 (slot 0)
    }
    // remote destinations for act lanes
    unsigned int dstH[2], dstB[2];
    if (tid < 64) {
        unsigned int h0 = smem_u32(&hbuf[0][q*64 + tid]);
        unsigned int h1 = smem_u32(&hbuf[1][q*64 + tid]);
        unsigned int pr = q ^ 1;
        dstH[0] = mapa_u32(h0, pr);
        dstH[1] = mapa_u32(h1, pr);
        dstB[0] = mapa_u32(barF_loc,     pr);
        dstB[1] = mapa_u32(barF_loc + 8, pr);
    }
    __syncthreads();
    asm volatile("barrier.cluster.arrive.aligned;" ::: "memory");
    asm volatile("barrier.cluster.wait.aligned;"   ::: "memory");

    float* hout = hall + ((size_t)l*BT + b*TT + k*CC)*HH + q*64;
    int pF[2] = {0, 0};

    // ---------- Phase B: CC recurrence steps ----------
    #pragma unroll 1
    for (int s = 0; s < CC; s++) {
        const int sl = s & 1;
        if (s >= 1) {
            bar_wait_acq_cluster(barF_loc + 8*sl, pF[sl]); pF[sl] ^= 1;
            if (tid == 64 && s + 2 < CC) mbar_expect_tx(barF_loc + 8*sl, 256u);
        }
        // full 128-dot, warp-uniform broadcast LDS
        const ulonglong2* H = reinterpret_cast<const ulonglong2*>(&hbuf[sl][0]);
        unsigned long long a0 = 0ULL, a1 = 0ULL;
        #pragma unroll
        for (int i = 0; i < 32; i++) {
            ulonglong2 h2 = H[i];
            fma2(a0, w[2*i],   h2.x);
            fma2(a1, w[2*i+1], h2.y);
        }
        gates_s[tid] = gin_s[s*256 + tid]
            + __uint_as_float((unsigned)(a0 & 0xffffffffULL))
            + __uint_as_float((unsigned)(a0 >> 32))
            + __uint_as_float((unsigned)(a1 & 0xffffffffULL))
            + __uint_as_float((unsigned)(a1 >> 32));
        __syncthreads();

        if (tid < 64) {
            float gi = gates_s[tid],       gf = gates_s[64 + tid];
            float gg = gates_s[128 + tid], go = gates_s[192 + tid];
            float si = fsig(gi), sf = fsig(gf), so = fsig(go);
            float tg = 2.0f*fsig(2.0f*gg) - 1.0f;
            c = sf*c + si*tg;
            float tc = 2.0f*fsig(2.0f*c) - 1.0f;
            float hn = so*tc;
            if (s + 1 < CC) {
                int ns = (s + 1) & 1;
                st_async_f32(dstH[ns], hn, dstB[ns]);  // remote 64 via tx barrier
                hbuf[ns][q*64 + tid] = hn;             // own 64 via STS
            } else {
                hstate[sidx + q*64 + tid] = hn;
                cstate[sidx + q*64 + tid] = c;
            }
            hout[(size_t)s*HH + tid] = hn;
        }
        __syncthreads();   // own-h visibility for next step's dot
    }
    asm volatile("barrier.cluster.arrive.aligned;" ::: "memory");
    asm volatile("barrier.cluster.wait.aligned;"   ::: "memory");
}

// ---------------- fused attention: logits + softmax + map + context + fc ----------------
// one block per batch element, 256 threads
__global__ void __launch_bounds__(256) attn_fused(
    const float* __restrict__ ph, const float* __restrict__ px,
    const float* __restrict__ aw, const float* __restrict__ fc_w,
    const float* __restrict__ fc_b, float* __restrict__ out_map,
    float* __restrict__ out_fc)
{
    int b = blockIdx.x, tid = threadIdx.x;
    int w = tid >> 5, ln = tid & 31;
    __shared__ __align__(16) float aws[HH];
    __shared__ float s_s[TT];
    __shared__ float red[8];
    __shared__ float bc;
    __shared__ float ctx_s[HH];

    if (tid < HH) aws[tid] = aw[tid];
    __syncthreads();

    // logits: warp w handles rows t in [w*32, w*32+32)
    const float4* aw4 = reinterpret_cast<const float4*>(aws);
    float4 av = aw4[ln];
    #pragma unroll 1
    for (int i = 0; i < 32; i++) {
        int t = w*32 + i;
        const float4* p4 = reinterpret_cast<const float4*>(ph + ((size_t)(b*TT + t))*HH);
        const float4* x4 = reinterpret_cast<const float4*>(px + ((size_t)(b*TT + t))*HH);
        float4 a = p4[ln], c4 = x4[ln];
        float v = tanhf(a.x + c4.x)*av.x + tanhf(a.y + c4.y)*av.y
                + tanhf(a.z + c4.z)*av.z + tanhf(a.w + c4.w)*av.w;
        v = warpSum(v);
        if (ln == 0) s_s[t] = v;
    }
    __syncthreads();

    // softmax over 256 (one value per thread)
    float v = s_s[tid];
    float m = v;
    #pragma unroll
    for (int o = 16; o > 0; o >>= 1) m = fmaxf(m, __shfl_xor_sync(0xffffffffu, m, o));
    if (ln == 0) red[w] = m;
    __syncthreads();
    if (tid == 0) {
        float M = red[0];
        for (int i = 1; i < 8; i++) M = fmaxf(M, red[i]);
        bc = M;
    }
    __syncthreads();
    float e = expf(v - bc);
    float s = warpSum(e);
    if (ln == 0) red[w] = s;
    __syncthreads();
    if (tid == 0) {
        float S = 0.f;
        for (int i = 0; i < 8; i++) S += red[i];
        bc = S;
    }
    __syncthreads();
    float p = e / bc;
    s_s[tid] = p;
    __syncthreads();

    // attention map: out_map[b,t,d] = p[t]/128
    const float inv = 1.0f / (float)DD;
    const size_t base = (size_t)b*TT*DD;
    for (int idx = tid; idx < TT*DD; idx += 256)
        out_map[base + idx] = s_s[idx >> 7] * inv;

    // context[h] = sum_t ph[b,t,h]*p[t]
    if (tid < HH) {
        float acc = 0.f;
        const float* pb = ph + (size_t)b*TT*HH + tid;
        #pragma unroll 4
        for (int t = 0; t < TT; t++)
            acc += pb[(size_t)t*HH] * s_s[t];
        ctx_s[tid] = acc;
    }
    __syncthreads();
    if (tid < NC) {
        float acc = fc_b[tid];
        for (int kk = 0; kk < HH; kk++) acc += ctx_s[kk] * fc_w[tid*HH + kk];
        out_fc[b*NC + tid] = acc;
    }
}

// ---------------- launch ----------------
extern "C" void kernel_launch(void* const* d_in, const int* in_sizes, int n_in,
                              void* d_out, int out_size)
{
    (void)in_sizes; (void)n_in;
    const float* x        = (const float*)d_in[0];
    const float* Wih      = (const float*)d_in[1];
    const float* Whh      = (const float*)d_in[2];
    const float* bih      = (const float*)d_in[3];
    const float* bhh      = (const float*)d_in[4];
    const float* proj_h_w = (const float*)d_in[5];
    const float* proj_h_b = (const float*)d_in[6];
    const float* proj_x_w = (const float*)d_in[7];
    const float* proj_x_b = (const float*)d_in[8];
    const float* attn_w   = (const float*)d_in[9];
    const float* fc_w     = (const float*)d_in[10];
    const float* fc_b     = (const float*)d_in[11];

    float *p_x2, *p_gin, *p_hall, *p_hst, *p_cst, *p_ln, *p_ph, *p_px, *p_pxr, *p_fc_s, *p_map_s;
    cudaGetSymbolAddress((void**)&p_x2,   g_x2);
    cudaGetSymbolAddress((void**)&p_gin,  g_gin);
    cudaGetSymbolAddress((void**)&p_hall, g_hall);
    cudaGetSymbolAddress((void**)&p_hst,  g_hstate);
    cudaGetSymbolAddress((void**)&p_cst,  g_cstate);
    cudaGetSymbolAddress((void**)&p_ln,   g_ln);
    cudaGetSymbolAddress((void**)&p_ph,   g_ph);
    cudaGetSymbolAddress((void**)&p_px,   g_px);
    cudaGetSymbolAddress((void**)&p_pxr,  g_pxr);
    cudaGetSymbolAddress((void**)&p_fc_s, g_fc_scratch);
    cudaGetSymbolAddress((void**)&p_map_s, g_map_scratch);

    float* outf = (float*)d_out;
    float* out_fc;
    float* out_map;
    if (out_size >= BB*NC + BT*DD) { out_fc = outf;   out_map = outf + BB*NC; }
    else if (out_size == BT*DD)    { out_map = outf;  out_fc  = p_fc_s; }
    else                           { out_fc = outf;   out_map = p_map_s; }

    const int dynSmem = (CC*256 + CC*128) * 4;   // 49152 bytes
    cudaFuncSetAttribute(lstm_wave, cudaFuncAttributeMaxDynamicSharedMemorySize, dynSmem);

    stats_kernel<<<DD, 256>>>(x);
    norm1_kernel<<<BB*DD, 256>>>(x);

    // layer-0 input GEMM (with biases); layers 1-3 input transforms run in-wave
    gemm16_kernel<<<BT/16, GG>>>(p_x2, Wih, bih, bhh, p_gin, GG);

    for (int d = 0; d < NDIAG; d++) {
        int lmin = (d - (KK - 1) > 0) ? d - (KK - 1) : 0;
        int lmax = (d < LL - 1) ? d : LL - 1;
        int ncells = lmax - lmin + 1;
        lstm_wave<<<ncells*BB*2, 256, dynSmem>>>(lmin, d, p_gin, Wih, Whh, bih, bhh,
                                                 p_hall, p_hst, p_cst);
    }

    const float* lstm_out = p_hall + (size_t)3*BT*HH;
    instnorm_kernel<<<BB*HH, 256>>>(lstm_out, p_ln, HH);
    gemm16_kernel<<<BT/16, HH>>>(p_ln, proj_h_w, proj_h_b, nullptr, p_ph, HH);
    gemm16_kernel<<<BT/16, HH>>>(p_x2, proj_x_w, proj_x_b, nullptr, p_pxr, HH);
    instnorm_kernel<<<BB*HH, 256>>>(p_pxr, p_px, HH);

    attn_fused<<<BB, 256>>>(p_ph, p_px, attn_w, fc_w, fc_b, out_map, out_fc);
}

// round 8
// speedup vs baseline: 7.3342x; 1.0082x over previous
#include <cuda_runtime.h>
#include <math.h>
#include <stdint.h>

#define BB 16
#define TT 256
#define DD 128
#define HH 128
#define LL 4
#define GG (4*HH)      // 512 gates
#define NC 10
#define EPSF 1e-5f
#define BT (BB*TT)     // 4096
#define CC 32          // chunk length
#define KK (TT/CC)     // 8 chunks
#define NDIAG (LL+KK-1)

// ---------------- scratch (device globals; no allocation allowed) ----------------
__device__ float g_x2[BT*DD];
__device__ float g_gin[BT*GG];        // layer-0 input-gemm result (with biases)
__device__ float g_hall[LL*BT*HH];    // per-layer hidden outputs
__device__ float g_hstate[LL*BB*HH];  // chunk-boundary h
__device__ float g_cstate[LL*BB*HH];  // chunk-boundary c
__device__ float g_ph[BT*HH];
__device__ float g_pxr[BT*HH];
__device__ float g_mu[DD];
__device__ float g_sd[DD];
__device__ float g_hmu[BB*HH];        // lstm_out column stats
__device__ float g_hrs[BB*HH];
__device__ float g_fc_scratch[BB*NC];
__device__ float g_map_scratch[BT*DD];

// ---------------- helpers ----------------
__device__ __forceinline__ float warpSum(float v) {
    #pragma unroll
    for (int o = 16; o > 0; o >>= 1) v += __shfl_xor_sync(0xffffffffu, v, o);
    return v;
}
__device__ __forceinline__ float fsig(float x) {
    return __fdividef(1.0f, 1.0f + __expf(-x));
}
__device__ __forceinline__ unsigned int smem_u32(const void* p) {
    unsigned int a;
    asm("{ .reg .u64 t; cvta.to.shared.u64 t, %1; cvt.u32.u64 %0, t; }" : "=r"(a) : "l"(p));
    return a;
}
__device__ __forceinline__ unsigned int mapa_u32(unsigned int local, unsigned int rank) {
    unsigned int r;
    asm("mapa.shared::cluster.u32 %0, %1, %2;" : "=r"(r) : "r"(local), "r"(rank));
    return r;
}
__device__ __forceinline__ void fma2(unsigned long long& acc, unsigned long long a, unsigned long long b) {
    asm("fma.rn.f32x2 %0, %1, %2, %0;" : "+l"(acc) : "l"(a), "l"(b));
}
__device__ __forceinline__ void mbar_init(unsigned int addr, unsigned int cnt) {
    asm volatile("mbarrier.init.shared.b64 [%0], %1;" :: "r"(addr), "r"(cnt) : "memory");
}
__device__ __forceinline__ void mbar_expect_tx(unsigned int addr, unsigned int bytes) {
    asm volatile("mbarrier.arrive.expect_tx.shared.b64 _, [%0], %1;" :: "r"(addr), "r"(bytes) : "memory");
}
__device__ __forceinline__ void st_async_f32(unsigned int addr, float v, unsigned int mbar) {
    asm volatile("st.async.shared::cluster.mbarrier::complete_tx::bytes.b32 [%0], %1, [%2];"
                 :: "r"(addr), "r"(__float_as_uint(v)), "r"(mbar) : "memory");
}
// CTA-scope acquire is sufficient: st.async lands in OUR smem banks before the
// tx is accounted; no cluster-scope fence (avoids CCTL.IVALL per step).
__device__ __forceinline__ void bar_wait_acq_cta(unsigned int addr, int parity) {
    asm volatile(
        "{\n\t"
        ".reg .pred P;\n\t"
        "BWL_%=:\n\t"
        "mbarrier.try_wait.parity.acquire.cta.shared::cta.b64 P, [%0], %1, 0x989680;\n\t"
        "@P bra BWD_%=;\n\t"
        "bra BWL_%=;\n\t"
        "BWD_%=:\n\t"
        "}"
        :: "r"(addr), "r"(parity) : "memory");
}

// ---------------- per-feature global mean / std (ddof=1), std+EPS ----------------
__global__ void stats_kernel(const float* __restrict__ x) {
    int d = blockIdx.x;
    float s = 0.f, s2 = 0.f;
    for (int i = threadIdx.x; i < BT; i += blockDim.x) {
        float v = x[i*DD + d];
        s += v; s2 += v*v;
    }
    __shared__ float sh[64];
    s = warpSum(s); s2 = warpSum(s2);
    int w = threadIdx.x >> 5, ln = threadIdx.x & 31;
    if (ln == 0) { sh[w] = s; sh[32+w] = s2; }
    __syncthreads();
    if (threadIdx.x == 0) {
        float S = 0.f, S2 = 0.f;
        int nw = blockDim.x >> 5;
        for (int i = 0; i < nw; i++) { S += sh[i]; S2 += sh[32+i]; }
        float m = S / (float)BT;
        float var = (S2 - (float)BT*m*m) / ((float)BT - 1.0f);
        g_mu[d] = m;
        g_sd[d] = sqrtf(var) + EPSF;
    }
}

// ---------------- global normalize + instance norm over T, fused ----------------
__global__ void norm1_kernel(const float* __restrict__ x) {
    int b = blockIdx.x / DD, d = blockIdx.x % DD;
    int t = threadIdx.x;
    float mu = g_mu[d], sd = g_sd[d];
    float v = x[((b*TT) + t)*DD + d];
    float x1 = (v - mu) / sd;
    __shared__ float sh[16];
    float s = warpSum(x1), s2 = warpSum(x1*x1);
    int w = t >> 5, ln = t & 31;
    if (ln == 0) { sh[w] = s; sh[8+w] = s2; }
    __syncthreads();
    __shared__ float mm, rs;
    if (t == 0) {
        float S = 0.f, S2 = 0.f;
        for (int i = 0; i < 8; i++) { S += sh[i]; S2 += sh[8+i]; }
        float m = S / (float)TT;
        float var = S2 / (float)TT - m*m;
        mm = m; rs = rsqrtf(var + EPSF);
    }
    __syncthreads();
    g_x2[((b*TT) + t)*DD + d] = (x1 - mm) * rs;
}

// ---------------- column stats over T per (b,c): mu, rsqrt(var+eps) ----------------
// grid = BB, block = 256 (8 warps x 32 lanes); coalesced loads
__global__ void __launch_bounds__(256) colstats_kernel(
    const float* __restrict__ in, float* __restrict__ mu_o, float* __restrict__ rs_o)
{
    int b = blockIdx.x;
    int w = threadIdx.x >> 5, ln = threadIdx.x & 31;
    __shared__ float ws[8][HH], ws2[8][HH];
    float s[4] = {0,0,0,0}, s2[4] = {0,0,0,0};
    const float* base = in + (size_t)b*TT*HH;
    for (int t = w*32; t < (w+1)*32; t++) {
        const float* row = base + (size_t)t*HH;
        #pragma unroll
        for (int j = 0; j < 4; j++) {
            float v = row[ln + 32*j];
            s[j] += v; s2[j] += v*v;
        }
    }
    #pragma unroll
    for (int j = 0; j < 4; j++) { ws[w][ln + 32*j] = s[j]; ws2[w][ln + 32*j] = s2[j]; }
    __syncthreads();
    if (threadIdx.x < HH) {
        int c = threadIdx.x;
        float S = 0.f, S2 = 0.f;
        #pragma unroll
        for (int i = 0; i < 8; i++) { S += ws[i][c]; S2 += ws2[i][c]; }
        float m = S / (float)TT;
        float var = S2 / (float)TT - m*m;
        mu_o[b*HH + c] = m;
        rs_o[b*HH + c] = rsqrtf(var + EPSF);
    }
}

// ---------------- C[m,j] = sum_k A[m,k]*W[j,k] + b1[j] (+ b2[j]); K=128 ----------------
__global__ void __launch_bounds__(512, 2) gemm16_kernel(
    const float* __restrict__ A, const float* __restrict__ W,
    const float* __restrict__ b1, const float* __restrict__ b2,
    float* __restrict__ C, int N)
{
    __shared__ __align__(16) float As[16*128];
    int m0 = blockIdx.x * 16;
    for (int idx = threadIdx.x; idx < 16*128; idx += blockDim.x)
        As[idx] = A[m0*128 + idx];
    __syncthreads();
    int j = threadIdx.x;
    float bias = b1[j] + (b2 ? b2[j] : 0.0f);
    float acc[16];
    #pragma unroll
    for (int mi = 0; mi < 16; mi++) acc[mi] = bias;
    const float4* W4 = reinterpret_cast<const float4*>(W) + j*32;
    for (int k4 = 0; k4 < 32; k4++) {
        float4 w = W4[k4];
        #pragma unroll
        for (int mi = 0; mi < 16; mi++) {
            float4 a = *reinterpret_cast<const float4*>(&As[mi*128 + k4*4]);
            acc[mi] += a.x*w.x + a.y*w.y + a.z*w.z + a.w*w.w;
        }
    }
    #pragma unroll
    for (int mi = 0; mi < 16; mi++) C[(m0+mi)*N + j] = acc[mi];
}

// ---------------- gemm with inline column normalization of A ----------------
// A_norm[m,k] = (A[m,k]-mu[b,k])*rs[b,k], b = m/TT (16 rows never straddle b)
__global__ void __launch_bounds__(128, 4) gemm16n_kernel(
    const float* __restrict__ A, const float* __restrict__ W,
    const float* __restrict__ b1, const float* __restrict__ mu,
    const float* __restrict__ rs, float* __restrict__ C)
{
    __shared__ __align__(16) float As[16*128];
    __shared__ float mu_s[128], rs_s[128];
    int m0 = blockIdx.x * 16;
    int b = m0 / TT;
    if (threadIdx.x < 128) {
        mu_s[threadIdx.x] = mu[b*HH + threadIdx.x];
        rs_s[threadIdx.x] = rs[b*HH + threadIdx.x];
    }
    __syncthreads();
    for (int idx = threadIdx.x; idx < 16*128; idx += blockDim.x) {
        int k = idx & 127;
        As[idx] = (A[m0*128 + idx] - mu_s[k]) * rs_s[k];
    }
    __syncthreads();
    int j = threadIdx.x;
    float bias = b1[j];
    float acc[16];
    #pragma unroll
    for (int mi = 0; mi < 16; mi++) acc[mi] = bias;
    const float4* W4 = reinterpret_cast<const float4*>(W) + j*32;
    for (int k4 = 0; k4 < 32; k4++) {
        float4 w = W4[k4];
        #pragma unroll
        for (int mi = 0; mi < 16; mi++) {
            float4 a = *reinterpret_cast<const float4*>(&As[mi*128 + k4*4]);
            acc[mi] += a.x*w.x + a.y*w.y + a.z*w.z + a.w*w.w;
        }
    }
    #pragma unroll
    for (int mi = 0; mi < 16; mi++) C[(m0+mi)*HH + j] = acc[mi];
}

// ==================== chunked wavefront LSTM, full-row-per-thread ====================
// Per cell: 16 batches x 2-CTA cluster; CTA q owns units [64q,64q+64) = 256 rows.
// Weight row in regs reordered: w[0..31] = self-half k, w[32..63] = partner-half.
// Step: self-half dot BEFORE barrier wait (hides FMA under DSMEM transit).
__global__ void __launch_bounds__(256, 1) __cluster_dims__(2, 1, 1)
lstm_wave(int lmin, int d,
          const float* __restrict__ gin0,
          const float* __restrict__ Wih, const float* __restrict__ Whh,
          const float* __restrict__ bih, const float* __restrict__ bhh,
          float* __restrict__ hall, float* __restrict__ hstate, float* __restrict__ cstate)
{
    extern __shared__ float dyn[];
    float* gin_s = dyn;                // CC*256
    float* hin_s = dyn + CC*256;       // CC*128 (l>0)
    __shared__ __align__(16) float hbuf[2][HH];
    __shared__ float gates_s[256];
    __shared__ __align__(8) unsigned long long barF[2];

    const int cell = blockIdx.x >> 5;
    const int b    = (blockIdx.x >> 1) & 15;
    const int q    = blockIdx.x & 1;
    const int l    = lmin + cell;
    const int k    = d - l;
    const int tid  = threadIdx.x;
    const int gtype = tid >> 6, u = tid & 63;
    const int row_g = gtype*HH + q*64 + u;

    unsigned long long w[64];

    // ---------- Phase A: gin_s[s][tid] ----------
    if (l == 0) {
        const float* src = gin0 + ((size_t)(b*TT + k*CC))*GG + row_g;
        #pragma unroll 4
        for (int s = 0; s < CC; s++)
            gin_s[s*256 + tid] = src[(size_t)s*GG];
    } else {
        const float* hsrc = hall + ((size_t)(l-1)*BT + b*TT + k*CC)*HH;
        for (int idx = tid; idx < CC*HH; idx += 256) hin_s[idx] = hsrc[idx];
        {
            const unsigned long long* Wp =
                reinterpret_cast<const unsigned long long*>(Wih + ((size_t)l*GG + row_g)*HH);
            #pragma unroll
            for (int i = 0; i < 64; i++) w[i] = Wp[i];
        }
        float bias = bih[l*GG + row_g] + bhh[l*GG + row_g];
        __syncthreads();
        #pragma unroll 1
        for (int s = 0; s < CC; s++) {
            const ulonglong2* H = reinterpret_cast<const ulonglong2*>(&hin_s[s*HH]);
            unsigned long long a0 = 0ULL, a1 = 0ULL;
            #pragma unroll
            for (int i = 0; i < 32; i++) {
                ulonglong2 h2 = H[i];
                fma2(a0, w[2*i],   h2.x);
                fma2(a1, w[2*i+1], h2.y);
            }
            gin_s[s*256 + tid] = bias
                + __uint_as_float((unsigned)(a0 & 0xffffffffULL))
                + __uint_as_float((unsigned)(a0 >> 32))
                + __uint_as_float((unsigned)(a1 & 0xffffffffULL))
                + __uint_as_float((unsigned)(a1 >> 32));
        }
    }

    // ---------- Phase B setup: reload weights, self-half first ----------
    {
        const float* Wrow = Whh + ((size_t)l*GG + row_g)*HH;
        const unsigned long long* WpS =
            reinterpret_cast<const unsigned long long*>(Wrow + q*64);
        const unsigned long long* WpP =
            reinterpret_cast<const unsigned long long*>(Wrow + (q^1)*64);
        #pragma unroll
        for (int i = 0; i < 32; i++) { w[i] = WpS[i]; w[32+i] = WpP[i]; }
    }
    const int sidx = (l*BB + b)*HH;
    if (tid < HH) hbuf[0][tid] = (k == 0) ? 0.f : hstate[sidx + tid];
    float c = 0.f;
    if (tid < 64 && k > 0) c = cstate[sidx + q*64 + tid];

    const unsigned int barF_loc = smem_u32(&barF[0]);
    if (tid == 0) {
        mbar_init(barF_loc,     1);
        mbar_init(barF_loc + 8, 1);
    }
    __syncthreads();
    if (tid == 64) {
        mbar_expect_tx(barF_loc + 8, 256u);   // step 1 (slot 1)
        mbar_expect_tx(barF_loc,     256u);   // step 2 (slot 0)
    }
    unsigned int dstH[2], dstB[2];
    if (tid < 64) {
        unsigned int h0 = smem_u32(&hbuf[0][q*64 + tid]);
        unsigned int h1 = smem_u32(&hbuf[1][q*64 + tid]);
        unsigned int pr = q ^ 1;
        dstH[0] = mapa_u32(h0, pr);
        dstH[1] = mapa_u32(h1, pr);
        dstB[0] = mapa_u32(barF_loc,     pr);
        dstB[1] = mapa_u32(barF_loc + 8, pr);
    }
    __syncthreads();
    asm volatile("barrier.cluster.arrive.aligned;" ::: "memory");
    asm volatile("barrier.cluster.wait.aligned;"   ::: "memory");

    float* hout = hall + ((size_t)l*BT + b*TT + k*CC)*HH + q*64;
    int pF[2] = {0, 0};
    const int selfOff = q*64, partOff = (q^1)*64;

    // ---------- Phase B: CC recurrence steps ----------
    #pragma unroll 1
    for (int s = 0; s < CC; s++) {
        const int sl = s & 1;
        // self-half dot first (hbuf self half written locally + synced)
        unsigned long long a0 = 0ULL, a1 = 0ULL;
        {
            const ulonglong2* Hs = reinterpret_cast<const ulonglong2*>(&hbuf[sl][selfOff]);
            #pragma unroll
            for (int i = 0; i < 16; i++) {
                ulonglong2 h2 = Hs[i];
                fma2(a0, w[2*i],   h2.x);
                fma2(a1, w[2*i+1], h2.y);
            }
        }
        float gval = gin_s[s*256 + tid];
        if (s >= 1) {
            bar_wait_acq_cta(barF_loc + 8*sl, pF[sl]); pF[sl] ^= 1;
            if (tid == 64 && s + 2 < CC) mbar_expect_tx(barF_loc + 8*sl, 256u);
        }
        // partner-half dot
        {
            const ulonglong2* Hp = reinterpret_cast<const ulonglong2*>(&hbuf[sl][partOff]);
            #pragma unroll
            for (int i = 0; i < 16; i++) {
                ulonglong2 h2 = Hp[i];
                fma2(a0, w[32 + 2*i], h2.x);
                fma2(a1, w[33 + 2*i], h2.y);
            }
        }
        gates_s[tid] = gval
            + __uint_as_float((unsigned)(a0 & 0xffffffffULL))
            + __uint_as_float((unsigned)(a0 >> 32))
            + __uint_as_float((unsigned)(a1 & 0xffffffffULL))
            + __uint_as_float((unsigned)(a1 >> 32));
        __syncthreads();

        if (tid < 64) {
            float gi = gates_s[tid],       gf = gates_s[64 + tid];
            float gg = gates_s[128 + tid], go = gates_s[192 + tid];
            float si = fsig(gi), sf = fsig(gf), so = fsig(go);
            float tg = 2.0f*fsig(2.0f*gg) - 1.0f;
            c = sf*c + si*tg;
            float tc = 2.0f*fsig(2.0f*c) - 1.0f;
            float hn = so*tc;
            if (s + 1 < CC) {
                int ns = (s + 1) & 1;
                st_async_f32(dstH[ns], hn, dstB[ns]);  // remote 64 via tx barrier
                hbuf[ns][selfOff + tid] = hn;          // own 64 via STS
            } else {
                hstate[sidx + selfOff + tid] = hn;
                cstate[sidx + selfOff + tid] = c;
            }
            hout[(size_t)s*HH + tid] = hn;
        }
        __syncthreads();
    }
    asm volatile("barrier.cluster.arrive.aligned;" ::: "memory");
    asm volatile("barrier.cluster.wait.aligned;"   ::: "memory");
}

// ---------------- fused attention (+ inline px instance norm) ----------------
// one block per batch element, 256 threads
__global__ void __launch_bounds__(256) attn_fused(
    const float* __restrict__ ph, const float* __restrict__ pxr,
    const float* __restrict__ aw, const float* __restrict__ fc_w,
    const float* __restrict__ fc_b, float* __restrict__ out_map,
    float* __restrict__ out_fc)
{
    int b = blockIdx.x, tid = threadIdx.x;
    int w = tid >> 5, ln = tid & 31;
    __shared__ __align__(16) float aws[HH];
    __shared__ __align__(16) float mu_s[HH], rs_s[HH];
    __shared__ float ws[8][HH], ws2[8][HH];
    __shared__ float s_s[TT];
    __shared__ float red[8];
    __shared__ float bc;
    __shared__ float ctx_s[HH];

    if (tid < HH) aws[tid] = aw[tid];

    // px column stats (biased var, eps inside sqrt)
    {
        float s[4] = {0,0,0,0}, s2[4] = {0,0,0,0};
        const float* base = pxr + (size_t)b*TT*HH;
        for (int t = w*32; t < (w+1)*32; t++) {
            const float* row = base + (size_t)t*HH;
            #pragma unroll
            for (int j = 0; j < 4; j++) {
                float v = row[ln + 32*j];
                s[j] += v; s2[j] += v*v;
            }
        }
        #pragma unroll
        for (int j = 0; j < 4; j++) { ws[w][ln+32*j] = s[j]; ws2[w][ln+32*j] = s2[j]; }
        __syncthreads();
        if (tid < HH) {
            float S = 0.f, S2 = 0.f;
            #pragma unroll
            for (int i = 0; i < 8; i++) { S += ws[i][tid]; S2 += ws2[i][tid]; }
            float m = S / (float)TT;
            float var = S2 / (float)TT - m*m;
            mu_s[tid] = m;
            rs_s[tid] = rsqrtf(var + EPSF);
        }
    }
    __syncthreads();

    // logits: warp w handles rows t in [w*32, w*32+32)
    const float4* aw4 = reinterpret_cast<const float4*>(aws);
    const float4* mu4 = reinterpret_cast<const float4*>(mu_s);
    const float4* rs4 = reinterpret_cast<const float4*>(rs_s);
    float4 av = aw4[ln], am = mu4[ln], ar = rs4[ln];
    #pragma unroll 1
    for (int i = 0; i < 32; i++) {
        int t = w*32 + i;
        const float4* p4 = reinterpret_cast<const float4*>(ph + ((size_t)(b*TT + t))*HH);
        const float4* x4 = reinterpret_cast<const float4*>(pxr + ((size_t)(b*TT + t))*HH);
        float4 a = p4[ln], c4 = x4[ln];
        float v = tanhf(a.x + (c4.x - am.x)*ar.x)*av.x
                + tanhf(a.y + (c4.y - am.y)*ar.y)*av.y
                + tanhf(a.z + (c4.z - am.z)*ar.z)*av.z
                + tanhf(a.w + (c4.w - am.w)*ar.w)*av.w;
        v = warpSum(v);
        if (ln == 0) s_s[t] = v;
    }
    __syncthreads();

    // softmax over 256
    float v = s_s[tid];
    float m = v;
    #pragma unroll
    for (int o = 16; o > 0; o >>= 1) m = fmaxf(m, __shfl_xor_sync(0xffffffffu, m, o));
    if (ln == 0) red[w] = m;
    __syncthreads();
    if (tid == 0) {
        float M = red[0];
        for (int i = 1; i < 8; i++) M = fmaxf(M, red[i]);
        bc = M;
    }
    __syncthreads();
    float e = expf(v - bc);
    float s = warpSum(e);
    if (ln == 0) red[w] = s;
    __syncthreads();
    if (tid == 0) {
        float S = 0.f;
        for (int i = 0; i < 8; i++) S += red[i];
        bc = S;
    }
    __syncthreads();
    float p = e / bc;
    s_s[tid] = p;
    __syncthreads();

    // attention map
    const float inv = 1.0f / (float)DD;
    const size_t base = (size_t)b*TT*DD;
    for (int idx = tid; idx < TT*DD; idx += 256)
        out_map[base + idx] = s_s[idx >> 7] * inv;

    // context + fc
    if (tid < HH) {
        float acc = 0.f;
        const float* pb = ph + (size_t)b*TT*HH + tid;
        #pragma unroll 4
        for (int t = 0; t < TT; t++)
            acc += pb[(size_t)t*HH] * s_s[t];
        ctx_s[tid] = acc;
    }
    __syncthreads();
    if (tid < NC) {
        float acc = fc_b[tid];
        for (int kk = 0; kk < HH; kk++) acc += ctx_s[kk] * fc_w[tid*HH + kk];
        out_fc[b*NC + tid] = acc;
    }
}

// ---------------- launch ----------------
extern "C" void kernel_launch(void* const* d_in, const int* in_sizes, int n_in,
                              void* d_out, int out_size)
{
    (void)in_sizes; (void)n_in;
    const float* x        = (const float*)d_in[0];
    const float* Wih      = (const float*)d_in[1];
    const float* Whh      = (const float*)d_in[2];
    const float* bih      = (const float*)d_in[3];
    const float* bhh      = (const float*)d_in[4];
    const float* proj_h_w = (const float*)d_in[5];
    const float* proj_h_b = (const float*)d_in[6];
    const float* proj_x_w = (const float*)d_in[7];
    const float* proj_x_b = (const float*)d_in[8];
    const float* attn_w   = (const float*)d_in[9];
    const float* fc_w     = (const float*)d_in[10];
    const float* fc_b     = (const float*)d_in[11];

    float *p_x2, *p_gin, *p_hall, *p_hst, *p_cst, *p_ph, *p_pxr,
          *p_hmu, *p_hrs, *p_fc_s, *p_map_s;
    cudaGetSymbolAddress((void**)&p_x2,   g_x2);
    cudaGetSymbolAddress((void**)&p_gin,  g_gin);
    cudaGetSymbolAddress((void**)&p_hall, g_hall);
    cudaGetSymbolAddress((void**)&p_hst,  g_hstate);
    cudaGetSymbolAddress((void**)&p_cst,  g_cstate);
    cudaGetSymbolAddress((void**)&p_ph,   g_ph);
    cudaGetSymbolAddress((void**)&p_pxr,  g_pxr);
    cudaGetSymbolAddress((void**)&p_hmu,  g_hmu);
    cudaGetSymbolAddress((void**)&p_hrs,  g_hrs);
    cudaGetSymbolAddress((void**)&p_fc_s, g_fc_scratch);
    cudaGetSymbolAddress((void**)&p_map_s, g_map_scratch);

    float* outf = (float*)d_out;
    float* out_fc;
    float* out_map;
    if (out_size >= BB*NC + BT*DD) { out_fc = outf;   out_map = outf + BB*NC; }
    else if (out_size == BT*DD)    { out_map = outf;  out_fc  = p_fc_s; }
    else                           { out_fc = outf;   out_map = p_map_s; }

    const int dynSmem = (CC*256 + CC*128) * 4;   // 49152 bytes
    cudaFuncSetAttribute(lstm_wave, cudaFuncAttributeMaxDynamicSharedMemorySize, dynSmem);

    stats_kernel<<<DD, 256>>>(x);
    norm1_kernel<<<BB*DD, 256>>>(x);

    gemm16_kernel<<<BT/16, GG>>>(p_x2, Wih, bih, bhh, p_gin, GG);

    for (int d = 0; d < NDIAG; d++) {
        int lmin = (d - (KK - 1) > 0) ? d - (KK - 1) : 0;
        int lmax = (d < LL - 1) ? d : LL - 1;
        int ncells = lmax - lmin + 1;
        lstm_wave<<<ncells*BB*2, 256, dynSmem>>>(lmin, d, p_gin, Wih, Whh, bih, bhh,
                                                 p_hall, p_hst, p_cst);
    }

    const float* lstm_out = p_hall + (size_t)3*BT*HH;
    colstats_kernel<<<BB, 256>>>(lstm_out, p_hmu, p_hrs);
    gemm16n_kernel<<<BT/16, HH>>>(lstm_out, proj_h_w, proj_h_b, p_hmu, p_hrs, p_ph);
    gemm16_kernel<<<BT/16, HH>>>(p_x2, proj_x_w, proj_x_b, nullptr, p_pxr, HH);

    attn_fused<<<BB, 256>>>(p_ph, p_pxr, attn_w, fc_w, fc_b, out_map, out_fc);
}

// round 9
// speedup vs baseline: 7.3968x; 1.0085x over previous
#include <cuda_runtime.h>
#include <math.h>
#include <stdint.h>

#define BB 16
#define TT 256
#define DD 128
#define HH 128
#define LL 4
#define GG (4*HH)      // 512 gates
#define NC 10
#define EPSF 1e-5f
#define BT (BB*TT)     // 4096
#define CC 32          // chunk length
#define KK (TT/CC)     // 8 chunks
#define NDIAG (LL+KK-1)

// ---------------- scratch (device globals; no allocation allowed) ----------------
__device__ float g_x2[BT*DD];
__device__ float g_gin[BT*GG];        // layer-0 input-gemm result (with biases)
__device__ float g_hall[LL*BT*HH];    // per-layer hidden outputs
__device__ float g_hstate[LL*BB*HH];  // chunk-boundary h
__device__ float g_cstate[LL*BB*HH];  // chunk-boundary c
__device__ float g_ph[BT*HH];
__device__ float g_pxr[BT*HH];
__device__ float g_mu[DD];
__device__ float g_sd[DD];
__device__ float g_hmu[BB*HH];        // lstm_out column stats
__device__ float g_hrs[BB*HH];
__device__ float g_fc_scratch[BB*NC];
__device__ float g_map_scratch[BT*DD];

// ---------------- helpers ----------------
__device__ __forceinline__ float warpSum(float v) {
    #pragma unroll
    for (int o = 16; o > 0; o >>= 1) v += __shfl_xor_sync(0xffffffffu, v, o);
    return v;
}
__device__ __forceinline__ float fsig(float x) {
    return __fdividef(1.0f, 1.0f + __expf(-x));
}
__device__ __forceinline__ unsigned int smem_u32(const void* p) {
    unsigned int a;
    asm("{ .reg .u64 t; cvta.to.shared.u64 t, %1; cvt.u32.u64 %0, t; }" : "=r"(a) : "l"(p));
    return a;
}
__device__ __forceinline__ unsigned int mapa_u32(unsigned int local, unsigned int rank) {
    unsigned int r;
    asm("mapa.shared::cluster.u32 %0, %1, %2;" : "=r"(r) : "r"(local), "r"(rank));
    return r;
}
__device__ __forceinline__ void fma2(unsigned long long& acc, unsigned long long a, unsigned long long b) {
    asm("fma.rn.f32x2 %0, %1, %2, %0;" : "+l"(acc) : "l"(a), "l"(b));
}
__device__ __forceinline__ void mbar_init(unsigned int addr, unsigned int cnt) {
    asm volatile("mbarrier.init.shared.b64 [%0], %1;" :: "r"(addr), "r"(cnt) : "memory");
}
__device__ __forceinline__ void mbar_expect_tx(unsigned int addr, unsigned int bytes) {
    asm volatile("mbarrier.arrive.expect_tx.shared.b64 _, [%0], %1;" :: "r"(addr), "r"(bytes) : "memory");
}
// single bulk DSMEM push: local smem -> peer smem, one tx-update at peer barrier
__device__ __forceinline__ void bulk_send(unsigned int dst_cluster, unsigned int src_cta,
                                          unsigned int bytes, unsigned int remote_mbar) {
    asm volatile("cp.async.bulk.shared::cluster.shared::cta.mbarrier::complete_tx::bytes "
                 "[%0], [%1], %2, [%3];"
                 :: "r"(dst_cluster), "r"(src_cta), "r"(bytes), "r"(remote_mbar) : "memory");
}
__device__ __forceinline__ void fence_proxy_async_cta() {
    asm volatile("fence.proxy.async.shared::cta;" ::: "memory");
}
__device__ __forceinline__ void bar_wait_acq_cta(unsigned int addr, int parity) {
    asm volatile(
        "{\n\t"
        ".reg .pred P;\n\t"
        "BWL_%=:\n\t"
        "mbarrier.try_wait.parity.acquire.cta.shared::cta.b64 P, [%0], %1, 0x989680;\n\t"
        "@P bra BWD_%=;\n\t"
        "bra BWL_%=;\n\t"
        "BWD_%=:\n\t"
        "}"
        :: "r"(addr), "r"(parity) : "memory");
}

// ---------------- per-feature global mean / std (ddof=1), std+EPS ----------------
__global__ void stats_kernel(const float* __restrict__ x) {
    int d = blockIdx.x;
    float s = 0.f, s2 = 0.f;
    for (int i = threadIdx.x; i < BT; i += blockDim.x) {
        float v = x[i*DD + d];
        s += v; s2 += v*v;
    }
    __shared__ float sh[64];
    s = warpSum(s); s2 = warpSum(s2);
    int w = threadIdx.x >> 5, ln = threadIdx.x & 31;
    if (ln == 0) { sh[w] = s; sh[32+w] = s2; }
    __syncthreads();
    if (threadIdx.x == 0) {
        float S = 0.f, S2 = 0.f;
        int nw = blockDim.x >> 5;
        for (int i = 0; i < nw; i++) { S += sh[i]; S2 += sh[32+i]; }
        float m = S / (float)BT;
        float var = (S2 - (float)BT*m*m) / ((float)BT - 1.0f);
        g_mu[d] = m;
        g_sd[d] = sqrtf(var) + EPSF;
    }
}

// ---------------- global normalize + instance norm over T, fused ----------------
__global__ void norm1_kernel(const float* __restrict__ x) {
    int b = blockIdx.x / DD, d = blockIdx.x % DD;
    int t = threadIdx.x;
    float mu = g_mu[d], sd = g_sd[d];
    float v = x[((b*TT) + t)*DD + d];
    float x1 = (v - mu) / sd;
    __shared__ float sh[16];
    float s = warpSum(x1), s2 = warpSum(x1*x1);
    int w = t >> 5, ln = t & 31;
    if (ln == 0) { sh[w] = s; sh[8+w] = s2; }
    __syncthreads();
    __shared__ float mm, rs;
    if (t == 0) {
        float S = 0.f, S2 = 0.f;
        for (int i = 0; i < 8; i++) { S += sh[i]; S2 += sh[8+i]; }
        float m = S / (float)TT;
        float var = S2 / (float)TT - m*m;
        mm = m; rs = rsqrtf(var + EPSF);
    }
    __syncthreads();
    g_x2[((b*TT) + t)*DD + d] = (x1 - mm) * rs;
}

// ---------------- column stats over T per (b,c): mu, rsqrt(var+eps) ----------------
__global__ void __launch_bounds__(256) colstats_kernel(
    const float* __restrict__ in, float* __restrict__ mu_o, float* __restrict__ rs_o)
{
    int b = blockIdx.x;
    int w = threadIdx.x >> 5, ln = threadIdx.x & 31;
    __shared__ float ws[8][HH], ws2[8][HH];
    float s[4] = {0,0,0,0}, s2[4] = {0,0,0,0};
    const float* base = in + (size_t)b*TT*HH;
    for (int t = w*32; t < (w+1)*32; t++) {
        const float* row = base + (size_t)t*HH;
        #pragma unroll
        for (int j = 0; j < 4; j++) {
            float v = row[ln + 32*j];
            s[j] += v; s2[j] += v*v;
        }
    }
    #pragma unroll
    for (int j = 0; j < 4; j++) { ws[w][ln + 32*j] = s[j]; ws2[w][ln + 32*j] = s2[j]; }
    __syncthreads();
    if (threadIdx.x < HH) {
        int c = threadIdx.x;
        float S = 0.f, S2 = 0.f;
        #pragma unroll
        for (int i = 0; i < 8; i++) { S += ws[i][c]; S2 += ws2[i][c]; }
        float m = S / (float)TT;
        float var = S2 / (float)TT - m*m;
        mu_o[b*HH + c] = m;
        rs_o[b*HH + c] = rsqrtf(var + EPSF);
    }
}

// ---------------- C[m,j] = sum_k A[m,k]*W[j,k] + b1[j] (+ b2[j]); K=128 ----------------
__global__ void __launch_bounds__(512, 2) gemm16_kernel(
    const float* __restrict__ A, const float* __restrict__ W,
    const float* __restrict__ b1, const float* __restrict__ b2,
    float* __restrict__ C, int N)
{
    __shared__ __align__(16) float As[16*128];
    int m0 = blockIdx.x * 16;
    for (int idx = threadIdx.x; idx < 16*128; idx += blockDim.x)
        As[idx] = A[m0*128 + idx];
    __syncthreads();
    int j = threadIdx.x;
    float bias = b1[j] + (b2 ? b2[j] : 0.0f);
    float acc[16];
    #pragma unroll
    for (int mi = 0; mi < 16; mi++) acc[mi] = bias;
    const float4* W4 = reinterpret_cast<const float4*>(W) + j*32;
    for (int k4 = 0; k4 < 32; k4++) {
        float4 w = W4[k4];
        #pragma unroll
        for (int mi = 0; mi < 16; mi++) {
            float4 a = *reinterpret_cast<const float4*>(&As[mi*128 + k4*4]);
            acc[mi] += a.x*w.x + a.y*w.y + a.z*w.z + a.w*w.w;
        }
    }
    #pragma unroll
    for (int mi = 0; mi < 16; mi++) C[(m0+mi)*N + j] = acc[mi];
}

// ---------------- gemm with inline column normalization of A ----------------
__global__ void __launch_bounds__(128, 4) gemm16n_kernel(
    const float* __restrict__ A, const float* __restrict__ W,
    const float* __restrict__ b1, const float* __restrict__ mu,
    const float* __restrict__ rs, float* __restrict__ C)
{
    __shared__ __align__(16) float As[16*128];
    __shared__ float mu_s[128], rs_s[128];
    int m0 = blockIdx.x * 16;
    int b = m0 / TT;
    if (threadIdx.x < 128) {
        mu_s[threadIdx.x] = mu[b*HH + threadIdx.x];
        rs_s[threadIdx.x] = rs[b*HH + threadIdx.x];
    }
    __syncthreads();
    for (int idx = threadIdx.x; idx < 16*128; idx += blockDim.x) {
        int k = idx & 127;
        As[idx] = (A[m0*128 + idx] - mu_s[k]) * rs_s[k];
    }
    __syncthreads();
    int j = threadIdx.x;
    float bias = b1[j];
    float acc[16];
    #pragma unroll
    for (int mi = 0; mi < 16; mi++) acc[mi] = bias;
    const float4* W4 = reinterpret_cast<const float4*>(W) + j*32;
    for (int k4 = 0; k4 < 32; k4++) {
        float4 w = W4[k4];
        #pragma unroll
        for (int mi = 0; mi < 16; mi++) {
            float4 a = *reinterpret_cast<const float4*>(&As[mi*128 + k4*4]);
            acc[mi] += a.x*w.x + a.y*w.y + a.z*w.z + a.w*w.w;
        }
    }
    #pragma unroll
    for (int mi = 0; mi < 16; mi++) C[(m0+mi)*HH + j] = acc[mi];
}

// ==================== chunked wavefront LSTM, bulk h-exchange ====================
// Per cell: 16 batches x 2-CTA cluster; CTA q owns units [64q,64q+64) = 256 rows.
// 256 threads, full 128-weight row per thread (regs). Per step the 64 new h values
// cross CTAs as ONE 256B cp.async.bulk (single tx-update) instead of 64 st.async.
__global__ void __launch_bounds__(256, 1) __cluster_dims__(2, 1, 1)
lstm_wave(int lmin, int d,
          const float* __restrict__ gin0,
          const float* __restrict__ Wih, const float* __restrict__ Whh,
          const float* __restrict__ bih, const float* __restrict__ bhh,
          float* __restrict__ hall, float* __restrict__ hstate, float* __restrict__ cstate)
{
    extern __shared__ float dyn[];
    float* gin_s = dyn;                // CC*256
    float* hin_s = dyn + CC*256;       // CC*128 (l>0)
    __shared__ __align__(16) float hbuf[2][HH];
    __shared__ float gates_s[256];
    __shared__ __align__(8) unsigned long long barF[2];

    const int cell = blockIdx.x >> 5;
    const int b    = (blockIdx.x >> 1) & 15;
    const int q    = blockIdx.x & 1;
    const int l    = lmin + cell;
    const int k    = d - l;
    const int tid  = threadIdx.x;
    const int gtype = tid >> 6, u = tid & 63;
    const int row_g = gtype*HH + q*64 + u;

    unsigned long long w[64];

    // ---------- Phase A: gin_s[s][tid] ----------
    if (l == 0) {
        const float* src = gin0 + ((size_t)(b*TT + k*CC))*GG + row_g;
        #pragma unroll 4
        for (int s = 0; s < CC; s++)
            gin_s[s*256 + tid] = src[(size_t)s*GG];
    } else {
        const float* hsrc = hall + ((size_t)(l-1)*BT + b*TT + k*CC)*HH;
        for (int idx = tid; idx < CC*HH; idx += 256) hin_s[idx] = hsrc[idx];
        {
            const unsigned long long* Wp =
                reinterpret_cast<const unsigned long long*>(Wih + ((size_t)l*GG + row_g)*HH);
            #pragma unroll
            for (int i = 0; i < 64; i++) w[i] = Wp[i];
        }
        float bias = bih[l*GG + row_g] + bhh[l*GG + row_g];
        __syncthreads();
        #pragma unroll 1
        for (int s = 0; s < CC; s++) {
            const ulonglong2* H = reinterpret_cast<const ulonglong2*>(&hin_s[s*HH]);
            unsigned long long a0 = 0ULL, a1 = 0ULL;
            #pragma unroll
            for (int i = 0; i < 32; i++) {
                ulonglong2 h2 = H[i];
                fma2(a0, w[2*i],   h2.x);
                fma2(a1, w[2*i+1], h2.y);
            }
            gin_s[s*256 + tid] = bias
                + __uint_as_float((unsigned)(a0 & 0xffffffffULL))
                + __uint_as_float((unsigned)(a0 >> 32))
                + __uint_as_float((unsigned)(a1 & 0xffffffffULL))
                + __uint_as_float((unsigned)(a1 >> 32));
        }
    }

    // ---------- Phase B setup: reload weights, self-half first ----------
    {
        const float* Wrow = Whh + ((size_t)l*GG + row_g)*HH;
        const unsigned long long* WpS =
            reinterpret_cast<const unsigned long long*>(Wrow + q*64);
        const unsigned long long* WpP =
            reinterpret_cast<const unsigned long long*>(Wrow + (q^1)*64);
        #pragma unroll
        for (int i = 0; i < 32; i++) { w[i] = WpS[i]; w[32+i] = WpP[i]; }
    }
    const int sidx = (l*BB + b)*HH;
    if (tid < HH) hbuf[0][tid] = (k == 0) ? 0.f : hstate[sidx + tid];
    float c = 0.f;
    if (tid < 64 && k > 0) c = cstate[sidx + q*64 + tid];

    const unsigned int barF_loc = smem_u32(&barF[0]);
    if (tid == 0) {
        mbar_init(barF_loc,     1);
        mbar_init(barF_loc + 8, 1);
    }
    __syncthreads();
    if (tid == 64) {
        mbar_expect_tx(barF_loc + 8, 256u);   // step 1 (slot 1)
        mbar_expect_tx(barF_loc,     256u);   // step 2 (slot 0)
    }
    // bulk-send addresses (elected thread only)
    unsigned int srcH[2], dstH[2], dstB[2];
    if (tid == 0) {
        unsigned int h0 = smem_u32(&hbuf[0][q*64]);
        unsigned int h1 = smem_u32(&hbuf[1][q*64]);
        unsigned int pr = q ^ 1;
        srcH[0] = h0;               srcH[1] = h1;
        dstH[0] = mapa_u32(h0, pr); dstH[1] = mapa_u32(h1, pr);
        dstB[0] = mapa_u32(barF_loc,     pr);
        dstB[1] = mapa_u32(barF_loc + 8, pr);
    }
    __syncthreads();
    asm volatile("barrier.cluster.arrive.aligned;" ::: "memory");
    asm volatile("barrier.cluster.wait.aligned;"   ::: "memory");

    float* hout = hall + ((size_t)l*BT + b*TT + k*CC)*HH + q*64;
    int pF[2] = {0, 0};
    const int selfOff = q*64, partOff = (q^1)*64;

    // ---------- Phase B: CC recurrence steps ----------
    #pragma unroll 1
    for (int s = 0; s < CC; s++) {
        const int sl = s & 1;
        // self-half dot first (hbuf self half written locally + synced)
        unsigned long long a0 = 0ULL, a1 = 0ULL;
        {
            const ulonglong2* Hs = reinterpret_cast<const ulonglong2*>(&hbuf[sl][selfOff]);
            #pragma unroll
            for (int i = 0; i < 16; i++) {
                ulonglong2 h2 = Hs[i];
                fma2(a0, w[2*i],   h2.x);
                fma2(a1, w[2*i+1], h2.y);
            }
        }
        float gval = gin_s[s*256 + tid];
        if (s >= 1) {
            bar_wait_acq_cta(barF_loc + 8*sl, pF[sl]); pF[sl] ^= 1;
            if (tid == 64 && s + 2 < CC) mbar_expect_tx(barF_loc + 8*sl, 256u);
        }
        // partner-half dot
        {
            const ulonglong2* Hp = reinterpret_cast<const ulonglong2*>(&hbuf[sl][partOff]);
            #pragma unroll
            for (int i = 0; i < 16; i++) {
                ulonglong2 h2 = Hp[i];
                fma2(a0, w[32 + 2*i], h2.x);
                fma2(a1, w[33 + 2*i], h2.y);
            }
        }
        gates_s[tid] = gval
            + __uint_as_float((unsigned)(a0 & 0xffffffffULL))
            + __uint_as_float((unsigned)(a0 >> 32))
            + __uint_as_float((unsigned)(a1 & 0xffffffffULL))
            + __uint_as_float((unsigned)(a1 >> 32));
        __syncthreads();

        if (tid < 64) {
            float gi = gates_s[tid],       gf = gates_s[64 + tid];
            float gg = gates_s[128 + tid], go = gates_s[192 + tid];
            float si = fsig(gi), sf = fsig(gf), so = fsig(go);
            float tg = 2.0f*fsig(2.0f*gg) - 1.0f;
            c = sf*c + si*tg;
            float tc = 2.0f*fsig(2.0f*c) - 1.0f;
            float hn = so*tc;
            if (s + 1 < CC) {
                hbuf[(s + 1) & 1][selfOff + tid] = hn;   // own 64 via STS (also bulk source)
            } else {
                hstate[sidx + selfOff + tid] = hn;
                cstate[sidx + selfOff + tid] = c;
            }
            hout[(size_t)s*HH + tid] = hn;
        }
        __syncthreads();
        if (tid == 0 && s + 1 < CC) {
            int ns = (s + 1) & 1;
            fence_proxy_async_cta();                     // order STS before async-proxy read
            bulk_send(dstH[ns], srcH[ns], 256u, dstB[ns]);
        }
    }
    asm volatile("barrier.cluster.arrive.aligned;" ::: "memory");
    asm volatile("barrier.cluster.wait.aligned;"   ::: "memory");
}

// ---------------- fused attention (+ inline px instance norm) ----------------
__global__ void __launch_bounds__(256) attn_fused(
    const float* __restrict__ ph, const float* __restrict__ pxr,
    const float* __restrict__ aw, const float* __restrict__ fc_w,
    const float* __restrict__ fc_b, float* __restrict__ out_map,
    float* __restrict__ out_fc)
{
    int b = blockIdx.x, tid = threadIdx.x;
    int w = tid >> 5, ln = tid & 31;
    __shared__ __align__(16) float aws[HH];
    __shared__ __align__(16) float mu_s[HH], rs_s[HH];
    __shared__ float ws[8][HH], ws2[8][HH];
    __shared__ float s_s[TT];
    __shared__ float red[8];
    __shared__ float bc;
    __shared__ float ctx2[2][HH];

    if (tid < HH) aws[tid] = aw[tid];

    // px column stats (biased var, eps inside sqrt)
    {
        float s[4] = {0,0,0,0}, s2[4] = {0,0,0,0};
        const float* base = pxr + (size_t)b*TT*HH;
        for (int t = w*32; t < (w+1)*32; t++) {
            const float* row = base + (size_t)t*HH;
            #pragma unroll
            for (int j = 0; j < 4; j++) {
                float v = row[ln + 32*j];
                s[j] += v; s2[j] += v*v;
            }
        }
        #pragma unroll
        for (int j = 0; j < 4; j++) { ws[w][ln+32*j] = s[j]; ws2[w][ln+32*j] = s2[j]; }
        __syncthreads();
        if (tid < HH) {
            float S = 0.f, S2 = 0.f;
            #pragma unroll
            for (int i = 0; i < 8; i++) { S += ws[i][tid]; S2 += ws2[i][tid]; }
            float m = S / (float)TT;
            float var = S2 / (float)TT - m*m;
            mu_s[tid] = m;
            rs_s[tid] = rsqrtf(var + EPSF);
        }
    }
    __syncthreads();

    // logits
    const float4* aw4 = reinterpret_cast<const float4*>(aws);
    const float4* mu4 = reinterpret_cast<const float4*>(mu_s);
    const float4* rs4 = reinterpret_cast<const float4*>(rs_s);
    float4 av = aw4[ln], am = mu4[ln], ar = rs4[ln];
    #pragma unroll 1
    for (int i = 0; i < 32; i++) {
        int t = w*32 + i;
        const float4* p4 = reinterpret_cast<const float4*>(ph + ((size_t)(b*TT + t))*HH);
        const float4* x4 = reinterpret_cast<const float4*>(pxr + ((size_t)(b*TT + t))*HH);
        float4 a = p4[ln], c4 = x4[ln];
        float v = tanhf(a.x + (c4.x - am.x)*ar.x)*av.x
                + tanhf(a.y + (c4.y - am.y)*ar.y)*av.y
                + tanhf(a.z + (c4.z - am.z)*ar.z)*av.z
                + tanhf(a.w + (c4.w - am.w)*ar.w)*av.w;
        v = warpSum(v);
        if (ln == 0) s_s[t] = v;
    }
    __syncthreads();

    // softmax over 256
    float v = s_s[tid];
    float m = v;
    #pragma unroll
    for (int o = 16; o > 0; o >>= 1) m = fmaxf(m, __shfl_xor_sync(0xffffffffu, m, o));
    if (ln == 0) red[w] = m;
    __syncthreads();
    if (tid == 0) {
        float M = red[0];
        for (int i = 1; i < 8; i++) M = fmaxf(M, red[i]);
        bc = M;
    }
    __syncthreads();
    float e = expf(v - bc);
    float s = warpSum(e);
    if (ln == 0) red[w] = s;
    __syncthreads();
    if (tid == 0) {
        float S = 0.f;
        for (int i = 0; i < 8; i++) S += red[i];
        bc = S;
    }
    __syncthreads();
    float p = e / bc;
    s_s[tid] = p;
    __syncthreads();

    // attention map
    const float inv = 1.0f / (float)DD;
    const size_t base = (size_t)b*TT*DD;
    for (int idx = tid; idx < TT*DD; idx += 256)
        out_map[base + idx] = s_s[idx >> 7] * inv;

    // context: all 256 threads (two t-halves)
    {
        int h = tid & 127, half = tid >> 7;
        float acc = 0.f;
        const float* pb = ph + (size_t)(b*TT + half*128)*HH + h;
        #pragma unroll 4
        for (int t = 0; t < 128; t++)
            acc += pb[(size_t)t*HH] * s_s[half*128 + t];
        ctx2[half][h] = acc;
    }
    __syncthreads();
    if (tid < NC) {
        float acc = fc_b[tid];
        for (int kk = 0; kk < HH; kk++)
            acc += (ctx2[0][kk] + ctx2[1][kk]) * fc_w[tid*HH + kk];
        out_fc[b*NC + tid] = acc;
    }
}

// ---------------- launch ----------------
extern "C" void kernel_launch(void* const* d_in, const int* in_sizes, int n_in,
                              void* d_out, int out_size)
{
    (void)in_sizes; (void)n_in;
    const float* x        = (const float*)d_in[0];
    const float* Wih      = (const float*)d_in[1];
    const float* Whh      = (const float*)d_in[2];
    const float* bih      = (const float*)d_in[3];
    const float* bhh      = (const float*)d_in[4];
    const float* proj_h_w = (const float*)d_in[5];
    const float* proj_h_b = (const float*)d_in[6];
    const float* proj_x_w = (const float*)d_in[7];
    const float* proj_x_b = (const float*)d_in[8];
    const float* attn_w   = (const float*)d_in[9];
    const float* fc_w     = (const float*)d_in[10];
    const float* fc_b     = (const float*)d_in[11];

    float *p_x2, *p_gin, *p_hall, *p_hst, *p_cst, *p_ph, *p_pxr,
          *p_hmu, *p_hrs, *p_fc_s, *p_map_s;
    cudaGetSymbolAddress((void**)&p_x2,   g_x2);
    cudaGetSymbolAddress((void**)&p_gin,  g_gin);
    cudaGetSymbolAddress((void**)&p_hall, g_hall);
    cudaGetSymbolAddress((void**)&p_hst,  g_hstate);
    cudaGetSymbolAddress((void**)&p_cst,  g_cstate);
    cudaGetSymbolAddress((void**)&p_ph,   g_ph);
    cudaGetSymbolAddress((void**)&p_pxr,  g_pxr);
    cudaGetSymbolAddress((void**)&p_hmu,  g_hmu);
    cudaGetSymbolAddress((void**)&p_hrs,  g_hrs);
    cudaGetSymbolAddress((void**)&p_fc_s, g_fc_scratch);
    cudaGetSymbolAddress((void**)&p_map_s, g_map_scratch);

    float* outf = (float*)d_out;
    float* out_fc;
    float* out_map;
    if (out_size >= BB*NC + BT*DD) { out_fc = outf;   out_map = outf + BB*NC; }
    else if (out_size == BT*DD)    { out_map = outf;  out_fc  = p_fc_s; }
    else                           { out_fc = outf;   out_map = p_map_s; }

    const int dynSmem = (CC*256 + CC*128) * 4;   // 49152 bytes
    cudaFuncSetAttribute(lstm_wave, cudaFuncAttributeMaxDynamicSharedMemorySize, dynSmem);

    stats_kernel<<<DD, 256>>>(x);
    norm1_kernel<<<BB*DD, 256>>>(x);

    gemm16_kernel<<<BT/16, GG>>>(p_x2, Wih, bih, bhh, p_gin, GG);

    for (int d = 0; d < NDIAG; d++) {
        int lmin = (d - (KK - 1) > 0) ? d - (KK - 1) : 0;
        int lmax = (d < LL - 1) ? d : LL - 1;
        int ncells = lmax - lmin + 1;
        lstm_wave<<<ncells*BB*2, 256, dynSmem>>>(lmin, d, p_gin, Wih, Whh, bih, bhh,
                                                 p_hall, p_hst, p_cst);
    }

    const float* lstm_out = p_hall + (size_t)3*BT*HH;
    colstats_kernel<<<BB, 256>>>(lstm_out, p_hmu, p_hrs);
    gemm16n_kernel<<<BT/16, HH>>>(lstm_out, proj_h_w, proj_h_b, p_hmu, p_hrs, p_ph);
    gemm16_kernel<<<BT/16, HH>>>(p_x2, proj_x_w, proj_x_b, nullptr, p_pxr, HH);

    attn_fused<<<BB, 256>>>(p_ph, p_pxr, attn_w, fc_w, fc_b, out_map, out_fc);
}

// round 10
// speedup vs baseline: 7.9282x; 1.0718x over previous
#include <cuda_runtime.h>
#include <math.h>
#include <stdint.h>

#define BB 16
#define TT 256
#define DD 128
#define HH 128
#define LL 4
#define GG (4*HH)      // 512 gates
#define NC 10
#define EPSF 1e-5f
#define BT (BB*TT)     // 4096
#define CC 8           // chunk length
#define KK (TT/CC)     // 32 chunks

// ---------------- scratch (device globals; no allocation allowed) ----------------
__device__ float g_x2[BT*DD];
__device__ float g_gin[BT*GG];        // layer-0 input-gemm result (with biases)
__device__ float g_hall[LL*BT*HH];    // per-layer hidden outputs
__device__ int   g_flag[LL*BB*KK*2];  // chunk-publish flags
__device__ float g_ph[BT*HH];
__device__ float g_pxr[BT*HH];
__device__ float g_mu[DD];
__device__ float g_sd[DD];
__device__ float g_hmu[BB*HH];
__device__ float g_hrs[BB*HH];
__device__ float g_fc_scratch[BB*NC];
__device__ float g_map_scratch[BT*DD];

// ---------------- helpers ----------------
__device__ __forceinline__ float warpSum(float v) {
    #pragma unroll
    for (int o = 16; o > 0; o >>= 1) v += __shfl_xor_sync(0xffffffffu, v, o);
    return v;
}
__device__ __forceinline__ float fsig(float x) {
    return __fdividef(1.0f, 1.0f + __expf(-x));
}
__device__ __forceinline__ unsigned int smem_u32(const void* p) {
    unsigned int a;
    asm("{ .reg .u64 t; cvta.to.shared.u64 t, %1; cvt.u32.u64 %0, t; }" : "=r"(a) : "l"(p));
    return a;
}
__device__ __forceinline__ unsigned int mapa_u32(unsigned int local, unsigned int rank) {
    unsigned int r;
    asm("mapa.shared::cluster.u32 %0, %1, %2;" : "=r"(r) : "r"(local), "r"(rank));
    return r;
}
__device__ __forceinline__ void fma2(unsigned long long& acc, unsigned long long a, unsigned long long b) {
    asm("fma.rn.f32x2 %0, %1, %2, %0;" : "+l"(acc) : "l"(a), "l"(b));
}
__device__ __forceinline__ void mbar_init(unsigned int addr, unsigned int cnt) {
    asm volatile("mbarrier.init.shared.b64 [%0], %1;" :: "r"(addr), "r"(cnt) : "memory");
}
__device__ __forceinline__ void mbar_expect_tx(unsigned int addr, unsigned int bytes) {
    asm volatile("mbarrier.arrive.expect_tx.shared.b64 _, [%0], %1;" :: "r"(addr), "r"(bytes) : "memory");
}
__device__ __forceinline__ void bulk_send(unsigned int dst_cluster, unsigned int src_cta,
                                          unsigned int bytes, unsigned int remote_mbar) {
    asm volatile("cp.async.bulk.shared::cluster.shared::cta.mbarrier::complete_tx::bytes "
                 "[%0], [%1], %2, [%3];"
                 :: "r"(dst_cluster), "r"(src_cta), "r"(bytes), "r"(remote_mbar) : "memory");
}
__device__ __forceinline__ void fence_proxy_async_cta() {
    asm volatile("fence.proxy.async.shared::cta;" ::: "memory");
}
__device__ __forceinline__ void bar_wait_acq_cta(unsigned int addr, int parity) {
    asm volatile(
        "{\n\t"
        ".reg .pred P;\n\t"
        "BWL_%=:\n\t"
        "mbarrier.try_wait.parity.acquire.cta.shared::cta.b64 P, [%0], %1, 0x989680;\n\t"
        "@P bra BWD_%=;\n\t"
        "bra BWL_%=;\n\t"
        "BWD_%=:\n\t"
        "}"
        :: "r"(addr), "r"(parity) : "memory");
}
__device__ __forceinline__ int ld_acquire(const int* p) {
    int v;
    asm volatile("ld.acquire.gpu.global.b32 %0, [%1];" : "=r"(v) : "l"(p) : "memory");
    return v;
}
__device__ __forceinline__ void st_release(int* p, int v) {
    asm volatile("st.release.gpu.global.b32 [%0], %1;" :: "l"(p), "r"(v) : "memory");
}

// ---------------- flag reset (graph-replay safe) ----------------
__global__ void zero_flags_kernel(int* flags) {
    for (int i = threadIdx.x; i < LL*BB*KK*2; i += blockDim.x) flags[i] = 0;
}

// ---------------- per-feature global mean / std (ddof=1), std+EPS ----------------
__global__ void stats_kernel(const float* __restrict__ x) {
    int d = blockIdx.x;
    float s = 0.f, s2 = 0.f;
    for (int i = threadIdx.x; i < BT; i += blockDim.x) {
        float v = x[i*DD + d];
        s += v; s2 += v*v;
    }
    __shared__ float sh[64];
    s = warpSum(s); s2 = warpSum(s2);
    int w = threadIdx.x >> 5, ln = threadIdx.x & 31;
    if (ln == 0) { sh[w] = s; sh[32+w] = s2; }
    __syncthreads();
    if (threadIdx.x == 0) {
        float S = 0.f, S2 = 0.f;
        int nw = blockDim.x >> 5;
        for (int i = 0; i < nw; i++) { S += sh[i]; S2 += sh[32+i]; }
        float m = S / (float)BT;
        float var = (S2 - (float)BT*m*m) / ((float)BT - 1.0f);
        g_mu[d] = m;
        g_sd[d] = sqrtf(var) + EPSF;
    }
}

// ---------------- global normalize + instance norm over T, fused ----------------
__global__ void norm1_kernel(const float* __restrict__ x) {
    int b = blockIdx.x / DD, d = blockIdx.x % DD;
    int t = threadIdx.x;
    float mu = g_mu[d], sd = g_sd[d];
    float v = x[((b*TT) + t)*DD + d];
    float x1 = (v - mu) / sd;
    __shared__ float sh[16];
    float s = warpSum(x1), s2 = warpSum(x1*x1);
    int w = t >> 5, ln = t & 31;
    if (ln == 0) { sh[w] = s; sh[8+w] = s2; }
    __syncthreads();
    __shared__ float mm, rs;
    if (t == 0) {
        float S = 0.f, S2 = 0.f;
        for (int i = 0; i < 8; i++) { S += sh[i]; S2 += sh[8+i]; }
        float m = S / (float)TT;
        float var = S2 / (float)TT - m*m;
        mm = m; rs = rsqrtf(var + EPSF);
    }
    __syncthreads();
    g_x2[((b*TT) + t)*DD + d] = (x1 - mm) * rs;
}

// ---------------- column stats over T per (b,c) ----------------
__global__ void __launch_bounds__(256) colstats_kernel(
    const float* __restrict__ in, float* __restrict__ mu_o, float* __restrict__ rs_o)
{
    int b = blockIdx.x;
    int w = threadIdx.x >> 5, ln = threadIdx.x & 31;
    __shared__ float ws[8][HH], ws2[8][HH];
    float s[4] = {0,0,0,0}, s2[4] = {0,0,0,0};
    const float* base = in + (size_t)b*TT*HH;
    for (int t = w*32; t < (w+1)*32; t++) {
        const float* row = base + (size_t)t*HH;
        #pragma unroll
        for (int j = 0; j < 4; j++) {
            float v = row[ln + 32*j];
            s[j] += v; s2[j] += v*v;
        }
    }
    #pragma unroll
    for (int j = 0; j < 4; j++) { ws[w][ln + 32*j] = s[j]; ws2[w][ln + 32*j] = s2[j]; }
    __syncthreads();
    if (threadIdx.x < HH) {
        int c = threadIdx.x;
        float S = 0.f, S2 = 0.f;
        #pragma unroll
        for (int i = 0; i < 8; i++) { S += ws[i][c]; S2 += ws2[i][c]; }
        float m = S / (float)TT;
        float var = S2 / (float)TT - m*m;
        mu_o[b*HH + c] = m;
        rs_o[b*HH + c] = rsqrtf(var + EPSF);
    }
}

// ---------------- C[m,j] = sum_k A[m,k]*W[j,k] + b1[j] (+ b2[j]); K=128 ----------------
__global__ void __launch_bounds__(512, 2) gemm16_kernel(
    const float* __restrict__ A, const float* __restrict__ W,
    const float* __restrict__ b1, const float* __restrict__ b2,
    float* __restrict__ C, int N)
{
    __shared__ __align__(16) float As[16*128];
    int m0 = blockIdx.x * 16;
    for (int idx = threadIdx.x; idx < 16*128; idx += blockDim.x)
        As[idx] = A[m0*128 + idx];
    __syncthreads();
    int j = threadIdx.x;
    float bias = b1[j] + (b2 ? b2[j] : 0.0f);
    float acc[16];
    #pragma unroll
    for (int mi = 0; mi < 16; mi++) acc[mi] = bias;
    const float4* W4 = reinterpret_cast<const float4*>(W) + j*32;
    for (int k4 = 0; k4 < 32; k4++) {
        float4 w = W4[k4];
        #pragma unroll
        for (int mi = 0; mi < 16; mi++) {
            float4 a = *reinterpret_cast<const float4*>(&As[mi*128 + k4*4]);
            acc[mi] += a.x*w.x + a.y*w.y + a.z*w.z + a.w*w.w;
        }
    }
    #pragma unroll
    for (int mi = 0; mi < 16; mi++) C[(m0+mi)*N + j] = acc[mi];
}

// ---------------- gemm with inline column normalization of A ----------------
__global__ void __launch_bounds__(128, 4) gemm16n_kernel(
    const float* __restrict__ A, const float* __restrict__ W,
    const float* __restrict__ b1, const float* __restrict__ mu,
    const float* __restrict__ rs, float* __restrict__ C)
{
    __shared__ __align__(16) float As[16*128];
    __shared__ float mu_s[128], rs_s[128];
    int m0 = blockIdx.x * 16;
    int b = m0 / TT;
    if (threadIdx.x < 128) {
        mu_s[threadIdx.x] = mu[b*HH + threadIdx.x];
        rs_s[threadIdx.x] = rs[b*HH + threadIdx.x];
    }
    __syncthreads();
    for (int idx = threadIdx.x; idx < 16*128; idx += blockDim.x) {
        int k = idx & 127;
        As[idx] = (A[m0*128 + idx] - mu_s[k]) * rs_s[k];
    }
    __syncthreads();
    int j = threadIdx.x;
    float bias = b1[j];
    float acc[16];
    #pragma unroll
    for (int mi = 0; mi < 16; mi++) acc[mi] = bias;
    const float4* W4 = reinterpret_cast<const float4*>(W) + j*32;
    for (int k4 = 0; k4 < 32; k4++) {
        float4 w = W4[k4];
        #pragma unroll
        for (int mi = 0; mi < 16; mi++) {
            float4 a = *reinterpret_cast<const float4*>(&As[mi*128 + k4*4]);
            acc[mi] += a.x*w.x + a.y*w.y + a.z*w.z + a.w*w.w;
        }
    }
    #pragma unroll
    for (int mi = 0; mi < 16; mi++) C[(m0+mi)*HH + j] = acc[mi];
}

// ==================== persistent wavefront LSTM ====================
// 64 clusters (cid = l*16+b) x 2 CTAs, all co-resident. Whh rows live in regs
// for the whole kernel; h/c carried across chunks; layer handoff via gmem
// flags (release/acquire) gating CC-step chunks. Phase A streams Wih (LDG.128).
__global__ void __launch_bounds__(256, 1) __cluster_dims__(2, 1, 1)
lstm_persist(const float* __restrict__ gin0,
             const float* __restrict__ Wih, const float* __restrict__ Whh,
             const float* __restrict__ bih, const float* __restrict__ bhh,
             float* __restrict__ hall, int* __restrict__ flags)
{
    __shared__ __align__(16) float hbuf[2][HH];
    __shared__ __align__(16) float hin_s[CC*HH];
    __shared__ float gates_s[256];
    __shared__ __align__(8) unsigned long long barF[2];

    const int cid = blockIdx.x >> 1;
    const int l   = cid >> 4;           // 0..3
    const int b   = cid & 15;
    const int q   = blockIdx.x & 1;
    const int tid = threadIdx.x;
    const int gtype = tid >> 6, u = tid & 63;
    const int row_g = gtype*HH + q*64 + u;

    // Whh row resident in registers, self k-half first
    unsigned long long w[64];
    {
        const float* Wrow = Whh + ((size_t)l*GG + row_g)*HH;
        const unsigned long long* WpS = reinterpret_cast<const unsigned long long*>(Wrow + q*64);
        const unsigned long long* WpP = reinterpret_cast<const unsigned long long*>(Wrow + (q^1)*64);
        #pragma unroll
        for (int i = 0; i < 32; i++) { w[i] = WpS[i]; w[32+i] = WpP[i]; }
    }
    const float bias = (l > 0) ? (bih[l*GG + row_g] + bhh[l*GG + row_g]) : 0.f;
    const float4* Wih4 = reinterpret_cast<const float4*>(Wih + ((size_t)l*GG + row_g)*HH);

    if (tid < HH) hbuf[0][tid] = 0.f;
    float c = 0.f;

    const unsigned int barF_loc = smem_u32(&barF[0]);
    if (tid == 0) {
        mbar_init(barF_loc,     1);
        mbar_init(barF_loc + 8, 1);
    }
    __syncthreads();
    if (tid == 64) {
        mbar_expect_tx(barF_loc + 8, 256u);   // t=1 (slot 1)
        mbar_expect_tx(barF_loc,     256u);   // t=2 (slot 0)
    }
    unsigned int srcH[2], dstH[2], dstB[2];
    if (tid == 0) {
        unsigned int h0 = smem_u32(&hbuf[0][q*64]);
        unsigned int h1 = smem_u32(&hbuf[1][q*64]);
        unsigned int pr = q ^ 1;
        srcH[0] = h0;               srcH[1] = h1;
        dstH[0] = mapa_u32(h0, pr); dstH[1] = mapa_u32(h1, pr);
        dstB[0] = mapa_u32(barF_loc,     pr);
        dstB[1] = mapa_u32(barF_loc + 8, pr);
    }
    __syncthreads();
    asm volatile("barrier.cluster.arrive.aligned;" ::: "memory");
    asm volatile("barrier.cluster.wait.aligned;"   ::: "memory");

    float* hout = hall + ((size_t)l*BT + b*TT)*HH + q*64;
    const float* gsrc = gin0 + ((size_t)b*TT)*GG + row_g;
    int pF[2] = {0, 0};
    const int selfOff = q*64, partOff = (q^1)*64;

    for (int k = 0; k < KK; k++) {
        // ---- acquire this chunk's layer input, build gate-input in regs ----
        float gacc[CC];
        if (l == 0) {
            #pragma unroll
            for (int s = 0; s < CC; s++)
                gacc[s] = __ldg(gsrc + (size_t)(k*CC + s)*GG);
        } else {
            if (tid == 0) {
                const int* f0 = flags + (((l-1)*BB + b)*KK + k)*2;
                while (ld_acquire(f0)     == 0) __nanosleep(128);
                while (ld_acquire(f0 + 1) == 0) __nanosleep(128);
            }
            __syncthreads();
            const float* hsrc = hall + ((size_t)(l-1)*BT + b*TT + k*CC)*HH;
            for (int idx = tid; idx < CC*HH; idx += 256) hin_s[idx] = hsrc[idx];
            __syncthreads();
            // Phase A: stream Wih row (32 x LDG.128), CC accumulators in regs
            unsigned long long acc[CC];
            #pragma unroll
            for (int s = 0; s < CC; s++) acc[s] = 0ULL;
            #pragma unroll 4
            for (int j = 0; j < 32; j++) {
                float4 wv = __ldg(&Wih4[j]);
                unsigned long long wA, wB;
                asm("mov.b64 %0, {%1, %2};" : "=l"(wA) : "f"(wv.x), "f"(wv.y));
                asm("mov.b64 %0, {%1, %2};" : "=l"(wB) : "f"(wv.z), "f"(wv.w));
                #pragma unroll
                for (int s = 0; s < CC; s++) {
                    const ulonglong2 hv = *reinterpret_cast<const ulonglong2*>(&hin_s[s*HH + 4*j]);
                    fma2(acc[s], wA, hv.x);
                    fma2(acc[s], wB, hv.y);
                }
            }
            #pragma unroll
            for (int s = 0; s < CC; s++)
                gacc[s] = bias
                    + __uint_as_float((unsigned)(acc[s] & 0xffffffffULL))
                    + __uint_as_float((unsigned)(acc[s] >> 32));
        }

        // ---- phase B: CC recurrence steps (global step t) ----
        #pragma unroll 1
        for (int s = 0; s < CC; s++) {
            const int t = k*CC + s;
            const int sl = t & 1;
            unsigned long long a0 = 0ULL, a1 = 0ULL;
            {
                const ulonglong2* Hs = reinterpret_cast<const ulonglong2*>(&hbuf[sl][selfOff]);
                #pragma unroll
                for (int i = 0; i < 16; i++) {
                    ulonglong2 h2 = Hs[i];
                    fma2(a0, w[2*i],   h2.x);
                    fma2(a1, w[2*i+1], h2.y);
                }
            }
            if (t >= 1) {
                bar_wait_acq_cta(barF_loc + 8*sl, pF[sl]); pF[sl] ^= 1;
                if (tid == 64 && t + 2 < TT) mbar_expect_tx(barF_loc + 8*sl, 256u);
            }
            {
                const ulonglong2* Hp = reinterpret_cast<const ulonglong2*>(&hbuf[sl][partOff]);
                #pragma unroll
                for (int i = 0; i < 16; i++) {
                    ulonglong2 h2 = Hp[i];
                    fma2(a0, w[32 + 2*i], h2.x);
                    fma2(a1, w[33 + 2*i], h2.y);
                }
            }
            gates_s[tid] = gacc[s]
                + __uint_as_float((unsigned)(a0 & 0xffffffffULL))
                + __uint_as_float((unsigned)(a0 >> 32))
                + __uint_as_float((unsigned)(a1 & 0xffffffffULL))
                + __uint_as_float((unsigned)(a1 >> 32));
            __syncthreads();

            if (tid < 64) {
                float gi = gates_s[tid],       gf = gates_s[64 + tid];
                float gg = gates_s[128 + tid], go = gates_s[192 + tid];
                float si = fsig(gi), sf = fsig(gf), so = fsig(go);
                float tg = 2.0f*fsig(2.0f*gg) - 1.0f;
                c = sf*c + si*tg;
                float tc = 2.0f*fsig(2.0f*c) - 1.0f;
                float hn = so*tc;
                if (t + 1 < TT) hbuf[(t + 1) & 1][selfOff + tid] = hn;
                hout[(size_t)t*HH + tid] = hn;
            }
            __syncthreads();
            if (tid == 0 && t + 1 < TT) {
                int ns = (t + 1) & 1;
                fence_proxy_async_cta();
                bulk_send(dstH[ns], srcH[ns], 256u, dstB[ns]);
            }
        }

        // ---- publish chunk to layer l+1 ----
        if (l < LL - 1) {
            if (tid == 0) {
                __threadfence();
                st_release(flags + ((l*BB + b)*KK + k)*2 + q, 1);
            }
        }
    }
    asm volatile("barrier.cluster.arrive.aligned;" ::: "memory");
    asm volatile("barrier.cluster.wait.aligned;"   ::: "memory");
}

// ---------------- fused attention (+ inline px instance norm) ----------------
__global__ void __launch_bounds__(256) attn_fused(
    const float* __restrict__ ph, const float* __restrict__ pxr,
    const float* __restrict__ aw, const float* __restrict__ fc_w,
    const float* __restrict__ fc_b, float* __restrict__ out_map,
    float* __restrict__ out_fc)
{
    int b = blockIdx.x, tid = threadIdx.x;
    int w = tid >> 5, ln = tid & 31;
    __shared__ __align__(16) float aws[HH];
    __shared__ __align__(16) float mu_s[HH], rs_s[HH];
    __shared__ float ws[8][HH], ws2[8][HH];
    __shared__ float s_s[TT];
    __shared__ float red[8];
    __shared__ float bc;
    __shared__ float ctx2[2][HH];

    if (tid < HH) aws[tid] = aw[tid];

    {
        float s[4] = {0,0,0,0}, s2[4] = {0,0,0,0};
        const float* base = pxr + (size_t)b*TT*HH;
        for (int t = w*32; t < (w+1)*32; t++) {
            const float* row = base + (size_t)t*HH;
            #pragma unroll
            for (int j = 0; j < 4; j++) {
                float v = row[ln + 32*j];
                s[j] += v; s2[j] += v*v;
            }
        }
        #pragma unroll
        for (int j = 0; j < 4; j++) { ws[w][ln+32*j] = s[j]; ws2[w][ln+32*j] = s2[j]; }
        __syncthreads();
        if (tid < HH) {
            float S = 0.f, S2 = 0.f;
            #pragma unroll
            for (int i = 0; i < 8; i++) { S += ws[i][tid]; S2 += ws2[i][tid]; }
            float m = S / (float)TT;
            float var = S2 / (float)TT - m*m;
            mu_s[tid] = m;
            rs_s[tid] = rsqrtf(var + EPSF);
        }
    }
    __syncthreads();

    const float4* aw4 = reinterpret_cast<const float4*>(aws);
    const float4* mu4 = reinterpret_cast<const float4*>(mu_s);
    const float4* rs4 = reinterpret_cast<const float4*>(rs_s);
    float4 av = aw4[ln], am = mu4[ln], ar = rs4[ln];
    #pragma unroll 1
    for (int i = 0; i < 32; i++) {
        int t = w*32 + i;
        const float4* p4 = reinterpret_cast<const float4*>(ph + ((size_t)(b*TT + t))*HH);
        const float4* x4 = reinterpret_cast<const float4*>(pxr + ((size_t)(b*TT + t))*HH);
        float4 a = p4[ln], c4 = x4[ln];
        float v = tanhf(a.x + (c4.x - am.x)*ar.x)*av.x
                + tanhf(a.y + (c4.y - am.y)*ar.y)*av.y
                + tanhf(a.z + (c4.z - am.z)*ar.z)*av.z
                + tanhf(a.w + (c4.w - am.w)*ar.w)*av.w;
        v = warpSum(v);
        if (ln == 0) s_s[t] = v;
    }
    __syncthreads();

    float v = s_s[tid];
    float m = v;
    #pragma unroll
    for (int o = 16; o > 0; o >>= 1) m = fmaxf(m, __shfl_xor_sync(0xffffffffu, m, o));
    if (ln == 0) red[w] = m;
    __syncthreads();
    if (tid == 0) {
        float M = red[0];
        for (int i = 1; i < 8; i++) M = fmaxf(M, red[i]);
        bc = M;
    }
    __syncthreads();
    float e = expf(v - bc);
    float s = warpSum(e);
    if (ln == 0) red[w] = s;
    __syncthreads();
    if (tid == 0) {
        float S = 0.f;
        for (int i = 0; i < 8; i++) S += red[i];
        bc = S;
    }
    __syncthreads();
    float p = e / bc;
    s_s[tid] = p;
    __syncthreads();

    const float inv = 1.0f / (float)DD;
    const size_t base = (size_t)b*TT*DD;
    for (int idx = tid; idx < TT*DD; idx += 256)
        out_map[base + idx] = s_s[idx >> 7] * inv;

    {
        int h = tid & 127, half = tid >> 7;
        float acc = 0.f;
        const float* pb = ph + (size_t)(b*TT + half*128)*HH + h;
        #pragma unroll 4
        for (int t = 0; t < 128; t++)
            acc += pb[(size_t)t*HH] * s_s[half*128 + t];
        ctx2[half][h] = acc;
    }
    __syncthreads();
    if (tid < NC) {
        float acc = fc_b[tid];
        for (int kk = 0; kk < HH; kk++)
            acc += (ctx2[0][kk] + ctx2[1][kk]) * fc_w[tid*HH + kk];
        out_fc[b*NC + tid] = acc;
    }
}

// ---------------- launch ----------------
extern "C" void kernel_launch(void* const* d_in, const int* in_sizes, int n_in,
                              void* d_out, int out_size)
{
    (void)in_sizes; (void)n_in;
    const float* x        = (const float*)d_in[0];
    const float* Wih      = (const float*)d_in[1];
    const float* Whh      = (const float*)d_in[2];
    const float* bih      = (const float*)d_in[3];
    const float* bhh      = (const float*)d_in[4];
    const float* proj_h_w = (const float*)d_in[5];
    const float* proj_h_b = (const float*)d_in[6];
    const float* proj_x_w = (const float*)d_in[7];
    const float* proj_x_b = (const float*)d_in[8];
    const float* attn_w   = (const float*)d_in[9];
    const float* fc_w     = (const float*)d_in[10];
    const float* fc_b     = (const float*)d_in[11];

    float *p_x2, *p_gin, *p_hall, *p_ph, *p_pxr, *p_hmu, *p_hrs, *p_fc_s, *p_map_s;
    int *p_flag;
    cudaGetSymbolAddress((void**)&p_x2,   g_x2);
    cudaGetSymbolAddress((void**)&p_gin,  g_gin);
    cudaGetSymbolAddress((void**)&p_hall, g_hall);
    cudaGetSymbolAddress((void**)&p_flag, g_flag);
    cudaGetSymbolAddress((void**)&p_ph,   g_ph);
    cudaGetSymbolAddress((void**)&p_pxr,  g_pxr);
    cudaGetSymbolAddress((void**)&p_hmu,  g_hmu);
    cudaGetSymbolAddress((void**)&p_hrs,  g_hrs);
    cudaGetSymbolAddress((void**)&p_fc_s, g_fc_scratch);
    cudaGetSymbolAddress((void**)&p_map_s, g_map_scratch);

    float* outf = (float*)d_out;
    float* out_fc;
    float* out_map;
    if (out_size >= BB*NC + BT*DD) { out_fc = outf;   out_map = outf + BB*NC; }
    else if (out_size == BT*DD)    { out_map = outf;  out_fc  = p_fc_s; }
    else                           { out_fc = outf;   out_map = p_map_s; }

    zero_flags_kernel<<<1, 256>>>(p_flag);
    stats_kernel<<<DD, 256>>>(x);
    norm1_kernel<<<BB*DD, 256>>>(x);

    gemm16_kernel<<<BT/16, GG>>>(p_x2, Wih, bih, bhh, p_gin, GG);

    lstm_persist<<<LL*BB*2, 256>>>(p_gin, Wih, Whh, bih, bhh, p_hall, p_flag);

    const float* lstm_out = p_hall + (size_t)3*BT*HH;
    colstats_kernel<<<BB, 256>>>(lstm_out, p_hmu, p_hrs);
    gemm16n_kernel<<<BT/16, HH>>>(lstm_out, proj_h_w, proj_h_b, p_hmu, p_hrs, p_ph);
    gemm16_kernel<<<BT/16, HH>>>(p_x2, proj_x_w, proj_x_b, nullptr, p_pxr, HH);

    attn_fused<<<BB, 256>>>(p_ph, p_pxr, attn_w, fc_w, fc_b, out_map, out_fc);
}

// round 11
// speedup vs baseline: 8.5270x; 1.0755x over previous
#include <cuda_runtime.h>
#include <math.h>
#include <stdint.h>

#define BB 16
#define TT 256
#define DD 128
#define HH 128
#define LL 4
#define GG (4*HH)      // 512 gates
#define NC 10
#define EPSF 1e-5f
#define BT (BB*TT)     // 4096
#define CC 8           // chunk length
#define KK (TT/CC)     // 32 chunks

// ---------------- scratch (device globals; no allocation allowed) ----------------
__device__ float g_x2[BT*DD];
__device__ float g_hall[LL*BT*HH];    // per-layer hidden outputs
__device__ int   g_flag[LL*BB*KK*2];  // chunk-publish flags
__device__ float g_ph[BT*HH];
__device__ float g_pxr[BT*HH];
__device__ float g_mu[DD];
__device__ float g_sd[DD];
__device__ float g_hmu[BB*HH];
__device__ float g_hrs[BB*HH];
__device__ float g_fc_scratch[BB*NC];
__device__ float g_map_scratch[BT*DD];

// ---------------- helpers ----------------
__device__ __forceinline__ float warpSum(float v) {
    #pragma unroll
    for (int o = 16; o > 0; o >>= 1) v += __shfl_xor_sync(0xffffffffu, v, o);
    return v;
}
// HW tanh (sm_75+): 1 MUFU op, ~2e-5 rel err
__device__ __forceinline__ float ftanh(float x) {
    float y;
    asm("tanh.approx.f32 %0, %1;" : "=f"(y) : "f"(x));
    return y;
}
__device__ __forceinline__ float fsig2(float x) {            // sigmoid via HW tanh
    return fmaf(ftanh(x * 0.5f), 0.5f, 0.5f);
}
__device__ __forceinline__ unsigned int smem_u32(const void* p) {
    unsigned int a;
    asm("{ .reg .u64 t; cvta.to.shared.u64 t, %1; cvt.u32.u64 %0, t; }" : "=r"(a) : "l"(p));
    return a;
}
__device__ __forceinline__ unsigned int mapa_u32(unsigned int local, unsigned int rank) {
    unsigned int r;
    asm("mapa.shared::cluster.u32 %0, %1, %2;" : "=r"(r) : "r"(local), "r"(rank));
    return r;
}
__device__ __forceinline__ void fma2(unsigned long long& acc, unsigned long long a, unsigned long long b) {
    asm("fma.rn.f32x2 %0, %1, %2, %0;" : "+l"(acc) : "l"(a), "l"(b));
}
__device__ __forceinline__ void mbar_init(unsigned int addr, unsigned int cnt) {
    asm volatile("mbarrier.init.shared.b64 [%0], %1;" :: "r"(addr), "r"(cnt) : "memory");
}
__device__ __forceinline__ void mbar_expect_tx(unsigned int addr, unsigned int bytes) {
    asm volatile("mbarrier.arrive.expect_tx.shared.b64 _, [%0], %1;" :: "r"(addr), "r"(bytes) : "memory");
}
__device__ __forceinline__ void bulk_send(unsigned int dst_cluster, unsigned int src_cta,
                                          unsigned int bytes, unsigned int remote_mbar) {
    asm volatile("cp.async.bulk.shared::cluster.shared::cta.mbarrier::complete_tx::bytes "
                 "[%0], [%1], %2, [%3];"
                 :: "r"(dst_cluster), "r"(src_cta), "r"(bytes), "r"(remote_mbar) : "memory");
}
__device__ __forceinline__ void fence_proxy_async_cta() {
    asm volatile("fence.proxy.async.shared::cta;" ::: "memory");
}
__device__ __forceinline__ void bar_wait_acq_cta(unsigned int addr, int parity) {
    asm volatile(
        "{\n\t"
        ".reg .pred P;\n\t"
        "BWL_%=:\n\t"
        "mbarrier.try_wait.parity.acquire.cta.shared::cta.b64 P, [%0], %1, 0x989680;\n\t"
        "@P bra BWD_%=;\n\t"
        "bra BWL_%=;\n\t"
        "BWD_%=:\n\t"
        "}"
        :: "r"(addr), "r"(parity) : "memory");
}
__device__ __forceinline__ int ld_acquire(const int* p) {
    int v;
    asm volatile("ld.acquire.gpu.global.b32 %0, [%1];" : "=r"(v) : "l"(p) : "memory");
    return v;
}
__device__ __forceinline__ void st_release(int* p, int v) {
    asm volatile("st.release.gpu.global.b32 [%0], %1;" :: "l"(p), "r"(v) : "memory");
}

// ---------------- flag reset (graph-replay safe) ----------------
__global__ void zero_flags_kernel(int* flags) {
    for (int i = threadIdx.x; i < LL*BB*KK*2; i += blockDim.x) flags[i] = 0;
}

// ---------------- per-feature global mean / std (ddof=1), std+EPS ----------------
__global__ void stats_kernel(const float* __restrict__ x) {
    int d = blockIdx.x;
    float s = 0.f, s2 = 0.f;
    for (int i = threadIdx.x; i < BT; i += blockDim.x) {
        float v = x[i*DD + d];
        s += v; s2 += v*v;
    }
    __shared__ float sh[64];
    s = warpSum(s); s2 = warpSum(s2);
    int w = threadIdx.x >> 5, ln = threadIdx.x & 31;
    if (ln == 0) { sh[w] = s; sh[32+w] = s2; }
    __syncthreads();
    if (threadIdx.x == 0) {
        float S = 0.f, S2 = 0.f;
        int nw = blockDim.x >> 5;
        for (int i = 0; i < nw; i++) { S += sh[i]; S2 += sh[32+i]; }
        float m = S / (float)BT;
        float var = (S2 - (float)BT*m*m) / ((float)BT - 1.0f);
        g_mu[d] = m;
        g_sd[d] = sqrtf(var) + EPSF;
    }
}

// ---------------- global normalize + instance norm over T, fused ----------------
__global__ void norm1_kernel(const float* __restrict__ x) {
    int b = blockIdx.x / DD, d = blockIdx.x % DD;
    int t = threadIdx.x;
    float mu = g_mu[d], sd = g_sd[d];
    float v = x[((b*TT) + t)*DD + d];
    float x1 = (v - mu) / sd;
    __shared__ float sh[16];
    float s = warpSum(x1), s2 = warpSum(x1*x1);
    int w = t >> 5, ln = t & 31;
    if (ln == 0) { sh[w] = s; sh[8+w] = s2; }
    __syncthreads();
    __shared__ float mm, rs;
    if (t == 0) {
        float S = 0.f, S2 = 0.f;
        for (int i = 0; i < 8; i++) { S += sh[i]; S2 += sh[8+i]; }
        float m = S / (float)TT;
        float var = S2 / (float)TT - m*m;
        mm = m; rs = rsqrtf(var + EPSF);
    }
    __syncthreads();
    g_x2[((b*TT) + t)*DD + d] = (x1 - mm) * rs;
}

// ---------------- column stats over T per (b,c) ----------------
__global__ void __launch_bounds__(256) colstats_kernel(
    const float* __restrict__ in, float* __restrict__ mu_o, float* __restrict__ rs_o)
{
    int b = blockIdx.x;
    int w = threadIdx.x >> 5, ln = threadIdx.x & 31;
    __shared__ float ws[8][HH], ws2[8][HH];
    float s[4] = {0,0,0,0}, s2[4] = {0,0,0,0};
    const float* base = in + (size_t)b*TT*HH;
    for (int t = w*32; t < (w+1)*32; t++) {
        const float* row = base + (size_t)t*HH;
        #pragma unroll
        for (int j = 0; j < 4; j++) {
            float v = row[ln + 32*j];
            s[j] += v; s2[j] += v*v;
        }
    }
    #pragma unroll
    for (int j = 0; j < 4; j++) { ws[w][ln + 32*j] = s[j]; ws2[w][ln + 32*j] = s2[j]; }
    __syncthreads();
    if (threadIdx.x < HH) {
        int c = threadIdx.x;
        float S = 0.f, S2 = 0.f;
        #pragma unroll
        for (int i = 0; i < 8; i++) { S += ws[i][c]; S2 += ws2[i][c]; }
        float m = S / (float)TT;
        float var = S2 / (float)TT - m*m;
        mu_o[b*HH + c] = m;
        rs_o[b*HH + c] = rsqrtf(var + EPSF);
    }
}

// ---------------- C[m,j] = sum_k A[m,k]*W[j,k] + b1[j]; K=128 ----------------
__global__ void __launch_bounds__(512, 2) gemm16_kernel(
    const float* __restrict__ A, const float* __restrict__ W,
    const float* __restrict__ b1, const float* __restrict__ b2,
    float* __restrict__ C, int N)
{
    __shared__ __align__(16) float As[16*128];
    int m0 = blockIdx.x * 16;
    for (int idx = threadIdx.x; idx < 16*128; idx += blockDim.x)
        As[idx] = A[m0*128 + idx];
    __syncthreads();
    int j = threadIdx.x;
    float bias = b1[j] + (b2 ? b2[j] : 0.0f);
    float acc[16];
    #pragma unroll
    for (int mi = 0; mi < 16; mi++) acc[mi] = bias;
    const float4* W4 = reinterpret_cast<const float4*>(W) + j*32;
    for (int k4 = 0; k4 < 32; k4++) {
        float4 w = W4[k4];
        #pragma unroll
        for (int mi = 0; mi < 16; mi++) {
            float4 a = *reinterpret_cast<const float4*>(&As[mi*128 + k4*4]);
            acc[mi] += a.x*w.x + a.y*w.y + a.z*w.z + a.w*w.w;
        }
    }
    #pragma unroll
    for (int mi = 0; mi < 16; mi++) C[(m0+mi)*N + j] = acc[mi];
}

// ---------------- gemm with inline column normalization of A ----------------
__global__ void __launch_bounds__(128, 4) gemm16n_kernel(
    const float* __restrict__ A, const float* __restrict__ W,
    const float* __restrict__ b1, const float* __restrict__ mu,
    const float* __restrict__ rs, float* __restrict__ C)
{
    __shared__ __align__(16) float As[16*128];
    __shared__ float mu_s[128], rs_s[128];
    int m0 = blockIdx.x * 16;
    int b = m0 / TT;
    if (threadIdx.x < 128) {
        mu_s[threadIdx.x] = mu[b*HH + threadIdx.x];
        rs_s[threadIdx.x] = rs[b*HH + threadIdx.x];
    }
    __syncthreads();
    for (int idx = threadIdx.x; idx < 16*128; idx += blockDim.x) {
        int k = idx & 127;
        As[idx] = (A[m0*128 + idx] - mu_s[k]) * rs_s[k];
    }
    __syncthreads();
    int j = threadIdx.x;
    float bias = b1[j];
    float acc[16];
    #pragma unroll
    for (int mi = 0; mi < 16; mi++) acc[mi] = bias;
    const float4* W4 = reinterpret_cast<const float4*>(W) + j*32;
    for (int k4 = 0; k4 < 32; k4++) {
        float4 w = W4[k4];
        #pragma unroll
        for (int mi = 0; mi < 16; mi++) {
            float4 a = *reinterpret_cast<const float4*>(&As[mi*128 + k4*4]);
            acc[mi] += a.x*w.x + a.y*w.y + a.z*w.z + a.w*w.w;
        }
    }
    #pragma unroll
    for (int mi = 0; mi < 16; mi++) C[(m0+mi)*HH + j] = acc[mi];
}

// ==================== persistent wavefront LSTM ====================
// 64 clusters (cid = l*16+b) x 2 CTAs, all co-resident. Whh rows in regs for the
// whole kernel; layer handoff via gmem flags gating CC-step chunks. Phase A
// streams Wih per chunk — for ALL layers (layer 0 consumes x2 directly; the
// standalone input GEMM launch is gone).
__global__ void __launch_bounds__(256, 1) __cluster_dims__(2, 1, 1)
lstm_persist(const float* __restrict__ x2,
             const float* __restrict__ Wih, const float* __restrict__ Whh,
             const float* __restrict__ bih, const float* __restrict__ bhh,
             float* __restrict__ hall, int* __restrict__ flags)
{
    __shared__ __align__(16) float hbuf[2][HH];
    __shared__ __align__(16) float hin_s[CC*HH];
    __shared__ float gates_s[256];
    __shared__ __align__(8) unsigned long long barF[2];

    const int cid = blockIdx.x >> 1;
    const int l   = cid >> 4;           // 0..3
    const int b   = cid & 15;
    const int q   = blockIdx.x & 1;
    const int tid = threadIdx.x;
    const int gtype = tid >> 6, u = tid & 63;
    const int row_g = gtype*HH + q*64 + u;

    unsigned long long w[64];
    {
        const float* Wrow = Whh + ((size_t)l*GG + row_g)*HH;
        const unsigned long long* WpS = reinterpret_cast<const unsigned long long*>(Wrow + q*64);
        const unsigned long long* WpP = reinterpret_cast<const unsigned long long*>(Wrow + (q^1)*64);
        #pragma unroll
        for (int i = 0; i < 32; i++) { w[i] = WpS[i]; w[32+i] = WpP[i]; }
    }
    const float bias = bih[l*GG + row_g] + bhh[l*GG + row_g];
    const float4* Wih4 = reinterpret_cast<const float4*>(Wih + ((size_t)l*GG + row_g)*HH);

    if (tid < HH) hbuf[0][tid] = 0.f;
    float c = 0.f;

    const unsigned int barF_loc = smem_u32(&barF[0]);
    if (tid == 0) {
        mbar_init(barF_loc,     1);
        mbar_init(barF_loc + 8, 1);
    }
    __syncthreads();
    if (tid == 64) {
        mbar_expect_tx(barF_loc + 8, 256u);
        mbar_expect_tx(barF_loc,     256u);
    }
    unsigned int srcH[2], dstH[2], dstB[2];
    if (tid == 0) {
        unsigned int h0 = smem_u32(&hbuf[0][q*64]);
        unsigned int h1 = smem_u32(&hbuf[1][q*64]);
        unsigned int pr = q ^ 1;
        srcH[0] = h0;               srcH[1] = h1;
        dstH[0] = mapa_u32(h0, pr); dstH[1] = mapa_u32(h1, pr);
        dstB[0] = mapa_u32(barF_loc,     pr);
        dstB[1] = mapa_u32(barF_loc + 8, pr);
    }
    __syncthreads();
    asm volatile("barrier.cluster.arrive.aligned;" ::: "memory");
    asm volatile("barrier.cluster.wait.aligned;"   ::: "memory");

    float* hout = hall + ((size_t)l*BT + b*TT)*HH + q*64;
    const float* in_base = (l == 0) ? (x2 + (size_t)b*TT*DD)
                                    : (hall + ((size_t)(l-1)*BT + b*TT)*HH);
    int pF[2] = {0, 0};
    const int selfOff = q*64, partOff = (q^1)*64;

    for (int k = 0; k < KK; k++) {
        // ---- acquire this chunk's input, compute gate-input in regs (phase A) ----
        if (l > 0) {
            if (tid == 0) {
                const int* f0 = flags + (((l-1)*BB + b)*KK + k)*2;
                while (ld_acquire(f0)     == 0) __nanosleep(128);
                while (ld_acquire(f0 + 1) == 0) __nanosleep(128);
            }
            __syncthreads();
        }
        const float* hsrc = in_base + (size_t)(k*CC)*HH;
        for (int idx = tid; idx < CC*HH; idx += 256) hin_s[idx] = hsrc[idx];
        __syncthreads();

        float gacc[CC];
        {
            unsigned long long acc[CC];
            #pragma unroll
            for (int s = 0; s < CC; s++) acc[s] = 0ULL;
            #pragma unroll 4
            for (int j = 0; j < 32; j++) {
                float4 wv = __ldg(&Wih4[j]);
                unsigned long long wA, wB;
                asm("mov.b64 %0, {%1, %2};" : "=l"(wA) : "f"(wv.x), "f"(wv.y));
                asm("mov.b64 %0, {%1, %2};" : "=l"(wB) : "f"(wv.z), "f"(wv.w));
                #pragma unroll
                for (int s = 0; s < CC; s++) {
                    const ulonglong2 hv = *reinterpret_cast<const ulonglong2*>(&hin_s[s*HH + 4*j]);
                    fma2(acc[s], wA, hv.x);
                    fma2(acc[s], wB, hv.y);
                }
            }
            #pragma unroll
            for (int s = 0; s < CC; s++)
                gacc[s] = bias
                    + __uint_as_float((unsigned)(acc[s] & 0xffffffffULL))
                    + __uint_as_float((unsigned)(acc[s] >> 32));
        }
        __syncthreads();   // hin_s reuse safety for next chunk

        // ---- phase B: CC recurrence steps ----
        #pragma unroll 1
        for (int s = 0; s < CC; s++) {
            const int t = k*CC + s;
            const int sl = t & 1;
            unsigned long long a0 = 0ULL, a1 = 0ULL;
            {
                const ulonglong2* Hs = reinterpret_cast<const ulonglong2*>(&hbuf[sl][selfOff]);
                #pragma unroll
                for (int i = 0; i < 16; i++) {
                    ulonglong2 h2 = Hs[i];
                    fma2(a0, w[2*i],   h2.x);
                    fma2(a1, w[2*i+1], h2.y);
                }
            }
            if (t >= 1) {
                bar_wait_acq_cta(barF_loc + 8*sl, pF[sl]); pF[sl] ^= 1;
                if (tid == 64 && t + 2 < TT) mbar_expect_tx(barF_loc + 8*sl, 256u);
            }
            {
                const ulonglong2* Hp = reinterpret_cast<const ulonglong2*>(&hbuf[sl][partOff]);
                #pragma unroll
                for (int i = 0; i < 16; i++) {
                    ulonglong2 h2 = Hp[i];
                    fma2(a0, w[32 + 2*i], h2.x);
                    fma2(a1, w[33 + 2*i], h2.y);
                }
            }
            gates_s[tid] = gacc[s]
                + __uint_as_float((unsigned)(a0 & 0xffffffffULL))
                + __uint_as_float((unsigned)(a0 >> 32))
                + __uint_as_float((unsigned)(a1 & 0xffffffffULL))
                + __uint_as_float((unsigned)(a1 >> 32));
            __syncthreads();

            if (tid < 64) {
                float gi = gates_s[tid],       gf = gates_s[64 + tid];
                float gg = gates_s[128 + tid], go = gates_s[192 + tid];
                float si = fsig2(gi), sf = fsig2(gf), so = fsig2(go);
                float tg = ftanh(gg);
                c = sf*c + si*tg;
                float hn = so * ftanh(c);
                if (t + 1 < TT) hbuf[(t + 1) & 1][selfOff + tid] = hn;
                hout[(size_t)t*HH + tid] = hn;
            }
            __syncthreads();
            if (tid == 0 && t + 1 < TT) {
                int ns = (t + 1) & 1;
                fence_proxy_async_cta();
                bulk_send(dstH[ns], srcH[ns], 256u, dstB[ns]);
            }
        }

        // ---- publish chunk to layer l+1 ----
        if (l < LL - 1 && tid == 0) {
            __threadfence();
            st_release(flags + ((l*BB + b)*KK + k)*2 + q, 1);
        }
    }
    asm volatile("barrier.cluster.arrive.aligned;" ::: "memory");
    asm volatile("barrier.cluster.wait.aligned;"   ::: "memory");
}

// ---------------- fused attention (+ inline px instance norm) ----------------
__global__ void __launch_bounds__(256) attn_fused(
    const float* __restrict__ ph, const float* __restrict__ pxr,
    const float* __restrict__ aw, const float* __restrict__ fc_w,
    const float* __restrict__ fc_b, float* __restrict__ out_map,
    float* __restrict__ out_fc)
{
    int b = blockIdx.x, tid = threadIdx.x;
    int w = tid >> 5, ln = tid & 31;
    __shared__ __align__(16) float aws[HH];
    __shared__ __align__(16) float mu_s[HH], rs_s[HH];
    __shared__ float ws[8][HH], ws2[8][HH];
    __shared__ float s_s[TT];
    __shared__ float red[8];
    __shared__ float bc;
    __shared__ float ctx2[2][HH];

    if (tid < HH) aws[tid] = aw[tid];

    {
        float s[4] = {0,0,0,0}, s2[4] = {0,0,0,0};
        const float* base = pxr + (size_t)b*TT*HH;
        for (int t = w*32; t < (w+1)*32; t++) {
            const float* row = base + (size_t)t*HH;
            #pragma unroll
            for (int j = 0; j < 4; j++) {
                float v = row[ln + 32*j];
                s[j] += v; s2[j] += v*v;
            }
        }
        #pragma unroll
        for (int j = 0; j < 4; j++) { ws[w][ln+32*j] = s[j]; ws2[w][ln+32*j] = s2[j]; }
        __syncthreads();
        if (tid < HH) {
            float S = 0.f, S2 = 0.f;
            #pragma unroll
            for (int i = 0; i < 8; i++) { S += ws[i][tid]; S2 += ws2[i][tid]; }
            float m = S / (float)TT;
            float var = S2 / (float)TT - m*m;
            mu_s[tid] = m;
            rs_s[tid] = rsqrtf(var + EPSF);
        }
    }
    __syncthreads();

    const float4* aw4 = reinterpret_cast<const float4*>(aws);
    const float4* mu4 = reinterpret_cast<const float4*>(mu_s);
    const float4* rs4 = reinterpret_cast<const float4*>(rs_s);
    float4 av = aw4[ln], am = mu4[ln], ar = rs4[ln];
    #pragma unroll 1
    for (int i = 0; i < 32; i++) {
        int t = w*32 + i;
        const float4* p4 = reinterpret_cast<const float4*>(ph + ((size_t)(b*TT + t))*HH);
        const float4* x4 = reinterpret_cast<const float4*>(pxr + ((size_t)(b*TT + t))*HH);
        float4 a = p4[ln], c4 = x4[ln];
        float v = ftanh(a.x + (c4.x - am.x)*ar.x)*av.x
                + ftanh(a.y + (c4.y - am.y)*ar.y)*av.y
                + ftanh(a.z + (c4.z - am.z)*ar.z)*av.z
                + ftanh(a.w + (c4.w - am.w)*ar.w)*av.w;
        v = warpSum(v);
        if (ln == 0) s_s[t] = v;
    }
    __syncthreads();

    float v = s_s[tid];
    float m = v;
    #pragma unroll
    for (int o = 16; o > 0; o >>= 1) m = fmaxf(m, __shfl_xor_sync(0xffffffffu, m, o));
    if (ln == 0) red[w] = m;
    __syncthreads();
    if (tid == 0) {
        float M = red[0];
        for (int i = 1; i < 8; i++) M = fmaxf(M, red[i]);
        bc = M;
    }
    __syncthreads();
    float e = expf(v - bc);
    float s = warpSum(e);
    if (ln == 0) red[w] = s;
    __syncthreads();
    if (tid == 0) {
        float S = 0.f;
        for (int i = 0; i < 8; i++) S += red[i];
        bc = S;
    }
    __syncthreads();
    float p = e / bc;
    s_s[tid] = p;
    __syncthreads();

    const float inv = 1.0f / (float)DD;
    const size_t base = (size_t)b*TT*DD;
    for (int idx = tid; idx < TT*DD; idx += 256)
        out_map[base + idx] = s_s[idx >> 7] * inv;

    {
        int h = tid & 127, half = tid >> 7;
        float acc = 0.f;
        const float* pb = ph + (size_t)(b*TT + half*128)*HH + h;
        #pragma unroll 4
        for (int t = 0; t < 128; t++)
            acc += pb[(size_t)t*HH] * s_s[half*128 + t];
        ctx2[half][h] = acc;
    }
    __syncthreads();
    if (tid < NC) {
        float acc = fc_b[tid];
        for (int kk = 0; kk < HH; kk++)
            acc += (ctx2[0][kk] + ctx2[1][kk]) * fc_w[tid*HH + kk];
        out_fc[b*NC + tid] = acc;
    }
}

// ---------------- launch ----------------
extern "C" void kernel_launch(void* const* d_in, const int* in_sizes, int n_in,
                              void* d_out, int out_size)
{
    (void)in_sizes; (void)n_in;
    const float* x        = (const float*)d_in[0];
    const float* Wih      = (const float*)d_in[1];
    const float* Whh      = (const float*)d_in[2];
    const float* bih      = (const float*)d_in[3];
    const float* bhh      = (const float*)d_in[4];
    const float* proj_h_w = (const float*)d_in[5];
    const float* proj_h_b = (const float*)d_in[6];
    const float* proj_x_w = (const float*)d_in[7];
    const float* proj_x_b = (const float*)d_in[8];
    const float* attn_w   = (const float*)d_in[9];
    const float* fc_w     = (const float*)d_in[10];
    const float* fc_b     = (const float*)d_in[11];

    float *p_x2, *p_hall, *p_ph, *p_pxr, *p_hmu, *p_hrs, *p_fc_s, *p_map_s;
    int *p_flag;
    cudaGetSymbolAddress((void**)&p_x2,   g_x2);
    cudaGetSymbolAddress((void**)&p_hall, g_hall);
    cudaGetSymbolAddress((void**)&p_flag, g_flag);
    cudaGetSymbolAddress((void**)&p_ph,   g_ph);
    cudaGetSymbolAddress((void**)&p_pxr,  g_pxr);
    cudaGetSymbolAddress((void**)&p_hmu,  g_hmu);
    cudaGetSymbolAddress((void**)&p_hrs,  g_hrs);
    cudaGetSymbolAddress((void**)&p_fc_s, g_fc_scratch);
    cudaGetSymbolAddress((void**)&p_map_s, g_map_scratch);

    float* outf = (float*)d_out;
    float* out_fc;
    float* out_map;
    if (out_size >= BB*NC + BT*DD) { out_fc = outf;   out_map = outf + BB*NC; }
    else if (out_size == BT*DD)    { out_map = outf;  out_fc  = p_fc_s; }
    else                           { out_fc = outf;   out_map = p_map_s; }

    zero_flags_kernel<<<1, 256>>>(p_flag);
    stats_kernel<<<DD, 256>>>(x);
    norm1_kernel<<<BB*DD, 256>>>(x);

    lstm_persist<<<LL*BB*2, 256>>>(p_x2, Wih, Whh, bih, bhh, p_hall, p_flag);

    const float* lstm_out = p_hall + (size_t)3*BT*HH;
    colstats_kernel<<<BB, 256>>>(lstm_out, p_hmu, p_hrs);
    gemm16n_kernel<<<BT/16, HH>>>(lstm_out, proj_h_w, proj_h_b, p_hmu, p_hrs, p_ph);
    gemm16_kernel<<<BT/16, HH>>>(p_x2, proj_x_w, proj_x_b, nullptr, p_pxr, HH);

    attn_fused<<<BB, 256>>>(p_ph, p_pxr, attn_w, fc_w, fc_b, out_map, out_fc);
}